// round 4
// baseline (speedup 1.0000x reference)
#include <cuda_runtime.h>
#include <math_constants.h>

#define SEQ  4096
#define HID  768
#define NB   8
#define KH   385   // HID/2 + 1 (Hermitian half + Nyquist)

typedef unsigned long long u64;

// ---------------------------------------------------------------- f32x2 helpers
__device__ __forceinline__ u64 pk2(float lo, float hi) {
    u64 r; asm("mov.b64 %0, {%1, %2};" : "=l"(r) : "f"(lo), "f"(hi)); return r;
}
__device__ __forceinline__ void upk2(u64 v, float& lo, float& hi) {
    asm("mov.b64 {%0, %1}, %2;" : "=f"(lo), "=f"(hi) : "l"(v));
}
__device__ __forceinline__ u64 ffma2(u64 a, u64 b, u64 c) {
    u64 d; asm("fma.rn.f32x2 %0, %1, %2, %3;" : "=l"(d) : "l"(a), "l"(b), "l"(c));
    return d;
}
__device__ __forceinline__ u64 fmul2(u64 a, u64 b) {
    u64 d; asm("mul.rn.f32x2 %0, %1, %2;" : "=l"(d) : "l"(a), "l"(b)); return d;
}

// ---------------------------------------------------------------- device state
__device__ float2 g_Y [NB * KH * SEQ];   // hidden-dim spectrum, [b][k][s]  (~101 MB)
__device__ float  g_Zr[NB * KH * SEQ];   // real 2D spectrum,    [b][k][m]  (~50 MB)
__device__ float2 g_w12[12 * 12];        // (c,s) of e^{-2pi i h1 r /12}
__device__ float4 g_w768q[768];          // (c,s,-s,c) of e^{-2pi i p /768}
__device__ float  g_c64 [4096];          // cos of e^{-2pi i ab/64}
__device__ float  g_s64 [4096];          // sin (negative-angle)
__device__ float  g_sn64[4096];          // -sin
__device__ float4 g_twq[4096];           // (c,s,-s,c) of e^{-2pi i ab/4096}

// ---------------------------------------------------------------- init tables
__global__ void k_init() {
    int i = blockIdx.x * blockDim.x + threadIdx.x;
    if (i < 144) {
        int h1 = i / 12, r = i - h1 * 12;
        float s, c;
        sincospif(-2.0f * (float)(h1 * r) / 12.0f, &s, &c);
        g_w12[i] = make_float2(c, s);
    }
    if (i < 768) {
        float s, c;
        sincospif(-2.0f * (float)i / 768.0f, &s, &c);
        g_w768q[i] = make_float4(c, s, -s, c);
    }
    if (i < 4096) {
        int a = i >> 6, b = i & 63;
        float s, c;
        sincospif(-2.0f * (float)(a * b) / 64.0f, &s, &c);
        g_c64[i] = c;  g_s64[i] = s;  g_sn64[i] = -s;
        sincospif(-(float)(a * b) / 2048.0f, &s, &c);   // -2ab/4096 in pi units
        g_twq[i] = make_float4(c, s, -s, c);
    }
}

// ------------------------------------------------- stage A: hidden-dim DFT(768)
// 768 = 64 x 12.  G[h0][r] = sum_{h1<12} x[h0+64*h1] * W12^{h1 r}
// Y[k] = sum_{h0<64} G[h0][k%12] * W768^{(h0 k)%768},   k = 0..384
__global__ __launch_bounds__(256) void k_stageA(const float* __restrict__ x) {
    __shared__ float  sx[4 * HID];    // 12 KB
    __shared__ float2 sG[4 * HID];    // 24 KB  [row][h0*12+r]
    int rowBase = blockIdx.x * 4;             // over b*SEQ + s
    int b    = rowBase >> 12;
    int srow = rowBase & 4095;
    const float* xp = x + (size_t)rowBase * HID;
    for (int i = threadIdx.x; i < 4 * HID; i += 256) sx[i] = xp[i];
    __syncthreads();

    for (int e = threadIdx.x; e < 4 * HID; e += 256) {
        int row = e / HID;
        int idx = e - row * HID;
        int h0 = idx / 12, r = idx - h0 * 12;
        u64 acc = 0ull;
        #pragma unroll
        for (int h1 = 0; h1 < 12; h1++) {
            float v = sx[row * HID + h0 + 64 * h1];
            u64 w = __ldg((const u64*)&g_w12[h1 * 12 + r]);
            acc = ffma2(pk2(v, v), w, acc);
        }
        float2 res; upk2(acc, res.x, res.y);
        sG[e] = res;
    }
    __syncthreads();

    for (int k = threadIdx.x; k < KH; k += 256) {
        int r = k % 12;
        u64 acc[4] = {0ull, 0ull, 0ull, 0ull};
        int p = 0;                      // (h0*k) % 768, incremental
        #pragma unroll 8
        for (int h0 = 0; h0 < 64; h0++) {
            ulonglong2 w = __ldg((const ulonglong2*)&g_w768q[p]);
            p += k; if (p >= 768) p -= 768;
            #pragma unroll
            for (int row = 0; row < 4; row++) {
                float2 g = sG[row * HID + h0 * 12 + r];
                acc[row] = ffma2(pk2(g.x, g.x), w.x, acc[row]);
                acc[row] = ffma2(pk2(g.y, g.y), w.y, acc[row]);
            }
        }
        #pragma unroll
        for (int row = 0; row < 4; row++) {
            float yr, yi; upk2(acc[row], yr, yi);
            size_t o = ((size_t)(b * KH + k)) * SEQ + (srow + row);
            g_Y[o] = make_float2(yr, yi);
        }
    }
}

// --------------------------------------- fused seq-dim FFT(4096) = 64 x 64
// Per block: one (b,k) column, staged in smem.
// Stage 1: A[s0][m0] = (sum_{s1} y[s0+64 s1] W64^{s1 m0}) * W4096^{s0 m0}
// Stage 2: Re(Z[m0+64 m1]) = sum_{s0} Re(A[s0][m0] W64^{s0 m1})
// f32x2-packed: stage1 packs column pairs of (re) and (im); stage2 packs
// column pairs of the real output. Result written COALESCED to g_Zr[b][k][m].
__global__ __launch_bounds__(256) void k_stageB() {
    __shared__ float2 sy[SEQ];   // 32 KB
    int col = blockIdx.x;                 // b*KH + k
    size_t base = (size_t)col * SEQ;
    const float4* syv = (const float4*)sy;

    for (int i = threadIdx.x; i < SEQ; i += 256) sy[i] = g_Y[base + i];
    __syncthreads();

    int t  = threadIdx.x;
    int i0 = (t >> 4) << 2;    // s0 tile base (stage1) / m1 tile base (stage2)
    int j0 = (t & 15) << 2;    // m0 tile base

    // ---- stage 1 ----
    u64 aRe[4][2], aIm[4][2];          // [r][c2]: columns j0+2c2, j0+2c2+1
    #pragma unroll
    for (int r = 0; r < 4; r++) { aRe[r][0]=aRe[r][1]=aIm[r][0]=aIm[r][1]=0ull; }

    #pragma unroll 4
    for (int s1 = 0; s1 < 64; s1++) {
        float4 ya = syv[(s1 << 5) + (i0 >> 1)];
        float4 yb = syv[(s1 << 5) + (i0 >> 1) + 1];
        u64 yx2[4] = {pk2(ya.x,ya.x), pk2(ya.z,ya.z), pk2(yb.x,yb.x), pk2(yb.z,yb.z)};
        u64 yy2[4] = {pk2(ya.y,ya.y), pk2(ya.w,ya.w), pk2(yb.y,yb.y), pk2(yb.w,yb.w)};
        int wb = (s1 << 6) + j0;
        u64 wc0 = __ldg((const u64*)&g_c64 [wb]);
        u64 wc1 = __ldg((const u64*)&g_c64 [wb + 2]);
        u64 ws0 = __ldg((const u64*)&g_s64 [wb]);
        u64 ws1 = __ldg((const u64*)&g_s64 [wb + 2]);
        u64 wn0 = __ldg((const u64*)&g_sn64[wb]);
        u64 wn1 = __ldg((const u64*)&g_sn64[wb + 2]);
        #pragma unroll
        for (int r = 0; r < 4; r++) {
            aRe[r][0] = ffma2(yx2[r], wc0, aRe[r][0]);
            aRe[r][0] = ffma2(yy2[r], wn0, aRe[r][0]);
            aRe[r][1] = ffma2(yx2[r], wc1, aRe[r][1]);
            aRe[r][1] = ffma2(yy2[r], wn1, aRe[r][1]);
            aIm[r][0] = ffma2(yx2[r], ws0, aIm[r][0]);
            aIm[r][0] = ffma2(yy2[r], wc0, aIm[r][0]);
            aIm[r][1] = ffma2(yx2[r], ws1, aIm[r][1]);
            aIm[r][1] = ffma2(yy2[r], wc1, aIm[r][1]);
        }
    }
    __syncthreads();            // all stage-1 reads of sy complete

    // twiddle + in-place writeback: element (s0 = i0+r, m0 = j0+2c2+u)
    #pragma unroll
    for (int r = 0; r < 4; r++)
        #pragma unroll
        for (int c2 = 0; c2 < 2; c2++) {
            float re0, re1, im0, im1;
            upk2(aRe[r][c2], re0, re1);
            upk2(aIm[r][c2], im0, im1);
            int idx0 = (i0 + r) * 64 + j0 + 2 * c2;
            ulonglong2 t0 = __ldg((const ulonglong2*)&g_twq[idx0]);
            ulonglong2 t1 = __ldg((const ulonglong2*)&g_twq[idx0 + 1]);
            u64 v0 = ffma2(pk2(im0, im0), t0.y, fmul2(pk2(re0, re0), t0.x));
            u64 v1 = ffma2(pk2(im1, im1), t1.y, fmul2(pk2(re1, re1), t1.x));
            ((u64*)sy)[idx0]     = v0;
            ((u64*)sy)[idx0 + 1] = v1;
        }
    __syncthreads();            // stage-1 writes visible

    // ---- stage 2 (real part only): m0 = j0+r, m1 = i0+2c2+u ----
    u64 z2[4][2];
    #pragma unroll
    for (int r = 0; r < 4; r++) { z2[r][0] = z2[r][1] = 0ull; }

    #pragma unroll 4
    for (int s0 = 0; s0 < 64; s0++) {
        float4 ba = syv[(s0 << 5) + (j0 >> 1)];
        float4 bb = syv[(s0 << 5) + (j0 >> 1) + 1];
        u64 bx2[4] = {pk2(ba.x,ba.x), pk2(ba.z,ba.z), pk2(bb.x,bb.x), pk2(bb.z,bb.z)};
        u64 by2[4] = {pk2(ba.y,ba.y), pk2(ba.w,ba.w), pk2(bb.y,bb.y), pk2(bb.w,bb.w)};
        int wb = (s0 << 6) + i0;
        u64 wc0 = __ldg((const u64*)&g_c64 [wb]);
        u64 wc1 = __ldg((const u64*)&g_c64 [wb + 2]);
        u64 wn0 = __ldg((const u64*)&g_sn64[wb]);
        u64 wn1 = __ldg((const u64*)&g_sn64[wb + 2]);
        #pragma unroll
        for (int r = 0; r < 4; r++) {
            z2[r][0] = ffma2(bx2[r], wc0, z2[r][0]);
            z2[r][0] = ffma2(by2[r], wn0, z2[r][0]);
            z2[r][1] = ffma2(bx2[r], wc1, z2[r][1]);
            z2[r][1] = ffma2(by2[r], wn1, z2[r][1]);
        }
    }
    __syncthreads();            // stage-2 reads of sy complete

    float* szr = (float*)sy;
    #pragma unroll
    for (int r = 0; r < 4; r++)
        #pragma unroll
        for (int c2 = 0; c2 < 2; c2++) {
            float z0, z1; upk2(z2[r][c2], z0, z1);
            int m0 = j0 + r, m1 = i0 + 2 * c2;
            szr[m0 + (m1 << 6)]       = z0;
            szr[m0 + ((m1 + 1) << 6)] = z1;
        }
    __syncthreads();

    for (int i = t; i < SEQ; i += 256)          // coalesced
        g_Zr[base + i] = szr[i];
}

// --------------------------------------- transpose + Hermitian mirror
// out[b][m][k] = Zr[b][k][m]                      for k <= 384
//             = Zr[b][768-k][(4096-m)%4096]       for k >= 385
// 64x64 tiles via smem; both reads and writes 128B-coalesced.
__global__ __launch_bounds__(256) void k_trans(float* __restrict__ out) {
    __shared__ float tile[64][65];
    int t  = threadIdx.x;
    int b  = blockIdx.z;
    int k0 = blockIdx.y << 6;
    int m0 = blockIdx.x << 6;

    int mm  = t & 63, kkb = t >> 6;
    #pragma unroll 4
    for (int it = 0; it < 16; it++) {
        int kk = kkb + (it << 2);
        int k  = k0 + kk;
        int m  = m0 + mm;
        float v;
        if (k < KH) {
            v = g_Zr[((size_t)(b * KH + k)) * SEQ + m];
        } else {
            int ks = HID - k;                 // 1..383
            int ms = (SEQ - m) & 4095;
            v = g_Zr[((size_t)(b * KH + ks)) * SEQ + ms];
        }
        tile[kk][mm] = v;
    }
    __syncthreads();

    int kk2 = t & 63, mmb = t >> 6;
    #pragma unroll 4
    for (int it = 0; it < 16; it++) {
        int mmw = mmb + (it << 2);
        out[((size_t)b * SEQ + m0 + mmw) * HID + k0 + kk2] = tile[kk2][mmw];
    }
}

extern "C" void kernel_launch(void* const* d_in, const int* in_sizes, int n_in,
                              void* d_out, int out_size) {
    (void)in_sizes; (void)n_in; (void)out_size;
    const float* x = (const float*)d_in[0];
    float* out = (float*)d_out;

    k_init   <<<16, 256>>>();
    k_stageA <<<NB * SEQ / 4, 256>>>(x);          // 8192 blocks
    k_stageB <<<NB * KH, 256>>>();                // 3080 blocks
    k_trans  <<<dim3(SEQ / 64, HID / 64, NB), 256>>>(out);   // 6144 blocks
}

// round 5
// speedup vs baseline: 1.1423x; 1.1423x over previous
#include <cuda_runtime.h>
#include <math_constants.h>

#define SEQ  4096
#define HID  768
#define NB   8
#define KH   385   // HID/2 + 1 (Hermitian half + Nyquist)

// ---------------------------------------------------------------- device state
__device__ float2 g_Y [NB * KH * SEQ];   // hidden-dim spectrum, [b][k][s]  (~101 MB)
__device__ float  g_Zr[NB * KH * SEQ];   // real 2D spectrum,    [b][k][m]  (~50 MB)
__device__ float2 g_w12[12 * 12];        // e^{-2pi i h1 r / 12}
__device__ float2 g_w64[64 * 64];        // e^{-2pi i a b / 64}
__device__ float2 g_tw[64 * 64];         // e^{-2pi i a b / 4096}
__device__ float2 g_w768[768];           // e^{-2pi i p / 768}

// ---------------------------------------------------------------- init tables
__global__ void k_init() {
    int i = blockIdx.x * blockDim.x + threadIdx.x;
    if (i < 144) {
        int h1 = i / 12, r = i - h1 * 12;
        float s, c;
        sincospif(-2.0f * (float)(h1 * r) / 12.0f, &s, &c);
        g_w12[i] = make_float2(c, s);
    }
    if (i < 768) {
        float s, c;
        sincospif(-2.0f * (float)i / 768.0f, &s, &c);
        g_w768[i] = make_float2(c, s);
    }
    if (i < 4096) {
        int a = i >> 6, b = i & 63;
        float s, c;
        sincospif(-2.0f * (float)(a * b) / 64.0f, &s, &c);
        g_w64[i] = make_float2(c, s);
        sincospif(-(float)(a * b) / 2048.0f, &s, &c);   // -2ab/4096 in pi units
        g_tw[i] = make_float2(c, s);
    }
}

// ------------------------------------------------- stage A: hidden-dim DFT(768)
// 768 = 64 x 12.  G[h0][r] = sum_{h1<12} x[h0+64*h1] * W12^{h1 r}
// Y[k] = sum_{h0<64} G[h0][k%12] * W768^{(h0 k)%768},   k = 0..384
__global__ __launch_bounds__(256) void k_stageA(const float* __restrict__ x) {
    __shared__ float  sx[4 * HID];    // 12 KB
    __shared__ float2 sG[4 * HID];    // 24 KB  [row][h0*12+r]
    int rowBase = blockIdx.x * 4;             // over b*SEQ + s
    int b    = rowBase >> 12;
    int srow = rowBase & 4095;
    const float* xp = x + (size_t)rowBase * HID;
    for (int i = threadIdx.x; i < 4 * HID; i += 256) sx[i] = xp[i];
    __syncthreads();

    for (int e = threadIdx.x; e < 4 * HID; e += 256) {
        int row = e / HID;
        int idx = e - row * HID;
        int h0 = idx / 12, r = idx - h0 * 12;
        float gr = 0.f, gi = 0.f;
        #pragma unroll
        for (int h1 = 0; h1 < 12; h1++) {
            float v = sx[row * HID + h0 + 64 * h1];
            float2 w = __ldg(&g_w12[h1 * 12 + r]);
            gr = fmaf(v, w.x, gr);
            gi = fmaf(v, w.y, gi);
        }
        sG[e] = make_float2(gr, gi);
    }
    __syncthreads();

    for (int k = threadIdx.x; k < KH; k += 256) {
        int r = k % 12;
        float yr[4] = {0.f, 0.f, 0.f, 0.f};
        float yi[4] = {0.f, 0.f, 0.f, 0.f};
        int p = 0;                      // (h0*k) % 768, incremental
        #pragma unroll 8
        for (int h0 = 0; h0 < 64; h0++) {
            float2 w = __ldg(&g_w768[p]);
            p += k; if (p >= 768) p -= 768;     // k <= 384 < 768, exact
            #pragma unroll
            for (int row = 0; row < 4; row++) {
                float2 g = sG[row * HID + h0 * 12 + r];
                yr[row] = fmaf(g.x, w.x, fmaf(-g.y, w.y, yr[row]));
                yi[row] = fmaf(g.x, w.y, fmaf( g.y, w.x, yi[row]));
            }
        }
        #pragma unroll
        for (int row = 0; row < 4; row++) {
            size_t o = ((size_t)(b * KH + k)) * SEQ + (srow + row);
            g_Y[o] = make_float2(yr[row], yi[row]);
        }
    }
}

// --------------------------------------- fused seq-dim FFT(4096) = 64 x 64
// Per block: one (b,k) column of 4096 complex values, staged in smem.
// Stage 1: A[s0][m0] = (sum_{s1} y[s0+64 s1] W64^{s1 m0}) * W4096^{s0 m0}
//          (accumulated in registers, written back to smem in place)
// Stage 2: Re(Z[m0+64 m1]) = sum_{s0} Re(A[s0][m0] * W64^{s0 m1})
// Each thread owns a 4x4 register tile in both stages.
// Output written COALESCED to g_Zr[b][k][m] (transpose kernel finishes it).
__global__ __launch_bounds__(256) void k_stageB() {
    __shared__ float2 sy[SEQ];   // 32 KB
    int col = blockIdx.x;                 // b*KH + k
    size_t base = (size_t)col * SEQ;

    const float4* syv = (const float4*)sy;        // 2 complex per float4
    const float4* gw  = (const float4*)g_w64;

    for (int i = threadIdx.x; i < SEQ; i += 256) sy[i] = g_Y[base + i];
    __syncthreads();

    int t  = threadIdx.x;
    int i0 = (t >> 4) << 2;    // s0 tile base (stage1) / m1 tile base (stage2)
    int j0 = (t & 15) << 2;    // m0 tile base

    // ---- stage 1 ----
    float2 acc[4][4];
    #pragma unroll
    for (int r = 0; r < 4; r++)
        #pragma unroll
        for (int c = 0; c < 4; c++) acc[r][c] = make_float2(0.f, 0.f);

    #pragma unroll 4
    for (int s1 = 0; s1 < 64; s1++) {
        float4 ya = syv[(s1 << 5) + (i0 >> 1)];
        float4 yb = syv[(s1 << 5) + (i0 >> 1) + 1];
        float4 wa = __ldg(&gw[(s1 << 5) + (j0 >> 1)]);
        float4 wb = __ldg(&gw[(s1 << 5) + (j0 >> 1) + 1]);
        float yx[4] = {ya.x, ya.z, yb.x, yb.z};
        float yy[4] = {ya.y, ya.w, yb.y, yb.w};
        float wx[4] = {wa.x, wa.z, wb.x, wb.z};
        float wy[4] = {wa.y, wa.w, wb.y, wb.w};
        #pragma unroll
        for (int r = 0; r < 4; r++)
            #pragma unroll
            for (int c = 0; c < 4; c++) {
                acc[r][c].x = fmaf(yx[r], wx[c], fmaf(-yy[r], wy[c], acc[r][c].x));
                acc[r][c].y = fmaf(yx[r], wy[c], fmaf( yy[r], wx[c], acc[r][c].y));
            }
    }
    __syncthreads();            // all stage-1 reads of sy complete

    #pragma unroll
    for (int r = 0; r < 4; r++)
        #pragma unroll
        for (int c = 0; c < 4; c++) {
            float2 tw = __ldg(&g_tw[(i0 + r) * 64 + (j0 + c)]);
            float2 v = acc[r][c];
            sy[(i0 + r) * 64 + (j0 + c)] =
                make_float2(fmaf(v.x, tw.x, -v.y * tw.y),
                            fmaf(v.x, tw.y,  v.y * tw.x));
        }
    __syncthreads();            // stage-1 writes visible

    // ---- stage 2 (real part only) ----
    int a0 = j0;                // m0 tile base
    int b0 = i0;                // m1 tile base
    float zr[4][4];
    #pragma unroll
    for (int r = 0; r < 4; r++)
        #pragma unroll
        for (int c = 0; c < 4; c++) zr[r][c] = 0.f;

    #pragma unroll 4
    for (int s0 = 0; s0 < 64; s0++) {
        float4 ba = syv[(s0 << 5) + (a0 >> 1)];
        float4 bb = syv[(s0 << 5) + (a0 >> 1) + 1];
        float4 wa = __ldg(&gw[(s0 << 5) + (b0 >> 1)]);
        float4 wb = __ldg(&gw[(s0 << 5) + (b0 >> 1) + 1]);
        float bx[4] = {ba.x, ba.z, bb.x, bb.z};
        float by[4] = {ba.y, ba.w, bb.y, bb.w};
        float wx[4] = {wa.x, wa.z, wb.x, wb.z};
        float wy[4] = {wa.y, wa.w, wb.y, wb.w};
        #pragma unroll
        for (int r = 0; r < 4; r++)
            #pragma unroll
            for (int c = 0; c < 4; c++)
                zr[r][c] = fmaf(bx[r], wx[c], fmaf(-by[r], wy[c], zr[r][c]));
    }
    __syncthreads();            // stage-2 reads of sy complete

    // stage output into smem (scatter within smem), then coalesced to g_Zr
    float* szr = (float*)sy;
    #pragma unroll
    for (int r = 0; r < 4; r++)
        #pragma unroll
        for (int c = 0; c < 4; c++) {
            int m = (a0 + r) + ((b0 + c) << 6);
            szr[m] = zr[r][c];
        }
    __syncthreads();

    for (int i = t; i < SEQ; i += 256)          // fully coalesced STG.128-able
        g_Zr[base + i] = szr[i];
}

// --------------------------------------- transpose + Hermitian mirror
// out[b][m][k] = Zr[b][k][m]                      for k <= 384
//             = Zr[b][768-k][(4096-m)%4096]       for k >= 385
// 64x64 tiles via smem; both reads and writes 128B-coalesced.
__global__ __launch_bounds__(256) void k_trans(float* __restrict__ out) {
    __shared__ float tile[64][65];
    int t  = threadIdx.x;
    int b  = blockIdx.z;
    int k0 = blockIdx.y << 6;
    int m0 = blockIdx.x << 6;

    int mm  = t & 63, kkb = t >> 6;
    #pragma unroll 4
    for (int it = 0; it < 16; it++) {
        int kk = kkb + (it << 2);
        int k  = k0 + kk;
        int m  = m0 + mm;
        float v;
        if (k < KH) {
            v = g_Zr[((size_t)(b * KH + k)) * SEQ + m];
        } else {
            int ks = HID - k;                 // 1..383
            int ms = (SEQ - m) & 4095;
            v = g_Zr[((size_t)(b * KH + ks)) * SEQ + ms];
        }
        tile[kk][mm] = v;
    }
    __syncthreads();

    int kk2 = t & 63, mmb = t >> 6;
    #pragma unroll 4
    for (int it = 0; it < 16; it++) {
        int mmw = mmb + (it << 2);
        out[((size_t)b * SEQ + m0 + mmw) * HID + k0 + kk2] = tile[kk2][mmw];
    }
}

extern "C" void kernel_launch(void* const* d_in, const int* in_sizes, int n_in,
                              void* d_out, int out_size) {
    (void)in_sizes; (void)n_in; (void)out_size;
    const float* x = (const float*)d_in[0];
    float* out = (float*)d_out;

    k_init   <<<16, 256>>>();
    k_stageA <<<NB * SEQ / 4, 256>>>(x);          // 8192 blocks
    k_stageB <<<NB * KH, 256>>>();                // 3080 blocks
    k_trans  <<<dim3(SEQ / 64, HID / 64, NB), 256>>>(out);   // 6144 blocks
}

// round 7
// speedup vs baseline: 1.5464x; 1.3537x over previous
#include <cuda_runtime.h>
#include <math_constants.h>

#define SEQ  4096
#define HID  768
#define NB   8
#define KH   385   // HID/2 + 1 (Hermitian half + Nyquist)

// ---------------------------------------------------------------- device state
__device__ float2 g_Y [NB * KH * SEQ];   // hidden-dim spectrum, [b][k][s]  (~101 MB)
__device__ float  g_Zr[NB * KH * SEQ];   // real 2D spectrum,    [b][k][m]  (~50 MB)
__device__ float2 g_w12[12 * 12];        // e^{-2pi i h1 r / 12}
__device__ float2 g_w768[768];           // e^{-2pi i p / 768}
__device__ float2 g_W4096[4096];         // e^{-2pi i p / 4096}

// ---------------------------------------------------------------- helpers
__device__ __forceinline__ float2 cadd(float2 a, float2 b){ return make_float2(a.x+b.x, a.y+b.y); }
__device__ __forceinline__ float2 csub(float2 a, float2 b){ return make_float2(a.x-b.x, a.y-b.y); }
__device__ __forceinline__ float2 mni (float2 a){ return make_float2(a.y, -a.x); }   // * (-i)
__device__ __forceinline__ float2 cmul(float2 a, float2 w){
    return make_float2(fmaf(a.x, w.x, -a.y * w.y), fmaf(a.x, w.y, a.y * w.x));
}
__device__ __forceinline__ int pad8(int p){ return p + (p >> 3); }

// 8-point DFT (negative exponent), in place. ~56 flops.
__device__ __forceinline__ void dft8(float2* v) {
    const float C = 0.70710678118654752f;
    float2 t0 = cadd(v[0], v[4]), t1 = csub(v[0], v[4]);
    float2 t2 = cadd(v[2], v[6]), t3 = csub(v[2], v[6]);
    float2 E0 = cadd(t0, t2), E2 = csub(t0, t2);
    float2 mt3 = mni(t3);
    float2 E1 = cadd(t1, mt3), E3 = csub(t1, mt3);
    float2 u0 = cadd(v[1], v[5]), u1 = csub(v[1], v[5]);
    float2 u2 = cadd(v[3], v[7]), u3 = csub(v[3], v[7]);
    float2 O0 = cadd(u0, u2), O2 = csub(u0, u2);
    float2 mu3 = mni(u3);
    float2 O1 = cadd(u1, mu3), O3 = csub(u1, mu3);
    float2 W1 = make_float2(C * (O1.x + O1.y), C * (O1.y - O1.x));   // W8^1 * O1
    float2 W2 = mni(O2);                                             // W8^2 * O2
    float2 W3 = make_float2(C * (O3.y - O3.x), -C * (O3.x + O3.y));  // W8^3 * O3
    v[0] = cadd(E0, O0);  v[4] = csub(E0, O0);
    v[1] = cadd(E1, W1);  v[5] = csub(E1, W1);
    v[2] = cadd(E2, W2);  v[6] = csub(E2, W2);
    v[3] = cadd(E3, W3);  v[7] = csub(E3, W3);
}

// One DIF radix-8 stage over 4096 points in padded smem.
// L = sub-DFT stride (= 4096/8^(s+1)), TSH = 8^s twiddle step.
// 512 butterflies; 256 threads, 2 each. Butterfly position sets are disjoint.
template<int L, int TSH>
__device__ __forceinline__ void fft_stage(float2* sy, int t) {
    #pragma unroll
    for (int rep = 0; rep < 2; rep++) {
        int b = t + rep * 256;
        int blk = b / L, i = b - blk * L;
        int basep = blk * (8 * L) + i;
        float2 v[8];
        #pragma unroll
        for (int j = 0; j < 8; j++) v[j] = sy[pad8(basep + L * j)];
        dft8(v);
        #pragma unroll
        for (int k = 1; k < 8; k++) {        // i*k*TSH < 4096 always
            float2 w = __ldg(&g_W4096[i * k * TSH]);
            v[k] = cmul(v[k], w);
        }
        #pragma unroll
        for (int k = 0; k < 8; k++) sy[pad8(basep + L * k)] = v[k];
    }
}

// ---------------------------------------------------------------- init tables
__global__ void k_init() {
    int i = blockIdx.x * blockDim.x + threadIdx.x;
    if (i < 144) {
        int h1 = i / 12, r = i - h1 * 12;
        float s, c;
        sincospif(-2.0f * (float)(h1 * r) / 12.0f, &s, &c);
        g_w12[i] = make_float2(c, s);
    }
    if (i < 768) {
        float s, c;
        sincospif(-2.0f * (float)i / 768.0f, &s, &c);
        g_w768[i] = make_float2(c, s);
    }
    if (i < 4096) {
        float s, c;
        sincospif(-(float)i / 2048.0f, &s, &c);    // -2*pi*i/4096
        g_W4096[i] = make_float2(c, s);
    }
}

// ------------------------------------------------- stage A: hidden-dim DFT(768)
// (unchanged from R4 best)
__global__ __launch_bounds__(256) void k_stageA(const float* __restrict__ x) {
    __shared__ float  sx[4 * HID];    // 12 KB
    __shared__ float2 sG[4 * HID];    // 24 KB  [row][h0*12+r]
    int rowBase = blockIdx.x * 4;
    int b    = rowBase >> 12;
    int srow = rowBase & 4095;
    const float* xp = x + (size_t)rowBase * HID;
    for (int i = threadIdx.x; i < 4 * HID; i += 256) sx[i] = xp[i];
    __syncthreads();

    for (int e = threadIdx.x; e < 4 * HID; e += 256) {
        int row = e / HID;
        int idx = e - row * HID;
        int h0 = idx / 12, r = idx - h0 * 12;
        float gr = 0.f, gi = 0.f;
        #pragma unroll
        for (int h1 = 0; h1 < 12; h1++) {
            float v = sx[row * HID + h0 + 64 * h1];
            float2 w = __ldg(&g_w12[h1 * 12 + r]);
            gr = fmaf(v, w.x, gr);
            gi = fmaf(v, w.y, gi);
        }
        sG[e] = make_float2(gr, gi);
    }
    __syncthreads();

    for (int k = threadIdx.x; k < KH; k += 256) {
        int r = k % 12;
        float yr[4] = {0.f, 0.f, 0.f, 0.f};
        float yi[4] = {0.f, 0.f, 0.f, 0.f};
        int p = 0;
        #pragma unroll 8
        for (int h0 = 0; h0 < 64; h0++) {
            float2 w = __ldg(&g_w768[p]);
            p += k; if (p >= 768) p -= 768;
            #pragma unroll
            for (int row = 0; row < 4; row++) {
                float2 g = sG[row * HID + h0 * 12 + r];
                yr[row] = fmaf(g.x, w.x, fmaf(-g.y, w.y, yr[row]));
                yi[row] = fmaf(g.x, w.y, fmaf( g.y, w.x, yi[row]));
            }
        }
        #pragma unroll
        for (int row = 0; row < 4; row++) {
            size_t o = ((size_t)(b * KH + k)) * SEQ + (srow + row);
            g_Y[o] = make_float2(yr[row], yi[row]);
        }
    }
}

// --------------------------------------- stage B: seq-dim FFT(4096), radix-8^4
// One (b,k) column per block. DIF: natural-order in, digit-reversed out;
// last stage keeps results in registers, real parts written digit-un-reversed
// into smem (conflict-free pad m+(m>>6)), then coalesced to g_Zr[b][k][m].
__global__ __launch_bounds__(256) void k_stageB() {
    __shared__ float2 sy[SEQ + SEQ / 8];   // 4608 * 8B = 36 KB, padded p+(p>>3)
    int col = blockIdx.x;                  // b*KH + k
    size_t base = (size_t)col * SEQ;
    int t = threadIdx.x;

    for (int n = t; n < SEQ; n += 256) sy[pad8(n)] = g_Y[base + n];
    __syncthreads();

    fft_stage<512, 1>(sy, t);  __syncthreads();
    fft_stage<64,  8>(sy, t);  __syncthreads();
    fft_stage<8,  64>(sy, t);  __syncthreads();

    // stage 3 (L=1, no twiddle) + digit-reversed real writeback
    float vx[16];
    int mb[2];
    #pragma unroll
    for (int rep = 0; rep < 2; rep++) {
        int b = t + rep * 256;
        float2 v[8];
        #pragma unroll
        for (int j = 0; j < 8; j++) v[j] = sy[pad8(8 * b + j)];
        dft8(v);
        int e0 = b & 7, e1 = (b >> 3) & 7, e2 = b >> 6;
        mb[rep] = e0 * 64 + e1 * 8 + e2;       // m = k*512 + mb
        #pragma unroll
        for (int k = 0; k < 8; k++) vx[rep * 8 + k] = v[k].x;
    }
    __syncthreads();                           // all stage-3 reads done

    float* szr = (float*)sy;                   // reuse as padded float buffer
    #pragma unroll
    for (int rep = 0; rep < 2; rep++)
        #pragma unroll
        for (int k = 0; k < 8; k++) {
            int m = k * 512 + mb[rep];
            szr[m + (m >> 6)] = vx[rep * 8 + k];
        }
    __syncthreads();

    for (int i = t; i < SEQ; i += 256)         // coalesced
        g_Zr[base + i] = szr[i + (i >> 6)];
}

// --------------------------------------- transpose + Hermitian mirror (unchanged)
// out[b][m][k] = Zr[b][k][m]  (k<=384),  = Zr[b][768-k][(4096-m)%4096]  (k>=385)
__global__ __launch_bounds__(256) void k_trans(float* __restrict__ out) {
    __shared__ float tile[64][65];
    int t  = threadIdx.x;
    int b  = blockIdx.z;
    int k0 = blockIdx.y << 6;
    int m0 = blockIdx.x << 6;

    int mm  = t & 63, kkb = t >> 6;
    #pragma unroll 4
    for (int it = 0; it < 16; it++) {
        int kk = kkb + (it << 2);
        int k  = k0 + kk;
        int m  = m0 + mm;
        float v;
        if (k < KH) {
            v = g_Zr[((size_t)(b * KH + k)) * SEQ + m];
        } else {
            int ks = HID - k;
            int ms = (SEQ - m) & 4095;
            v = g_Zr[((size_t)(b * KH + ks)) * SEQ + ms];
        }
        tile[kk][mm] = v;
    }
    __syncthreads();

    int kk2 = t & 63, mmb = t >> 6;
    #pragma unroll 4
    for (int it = 0; it < 16; it++) {
        int mmw = mmb + (it << 2);
        out[((size_t)b * SEQ + m0 + mmw) * HID + k0 + kk2] = tile[kk2][mmw];
    }
}

extern "C" void kernel_launch(void* const* d_in, const int* in_sizes, int n_in,
                              void* d_out, int out_size) {
    (void)in_sizes; (void)n_in; (void)out_size;
    const float* x = (const float*)d_in[0];
    float* out = (float*)d_out;

    k_init   <<<16, 256>>>();
    k_stageA <<<NB * SEQ / 4, 256>>>(x);          // 8192 blocks
    k_stageB <<<NB * KH, 256>>>();                // 3080 blocks
    k_trans  <<<dim3(SEQ / 64, HID / 64, NB), 256>>>(out);   // 6144 blocks
}

// round 8
// speedup vs baseline: 1.6818x; 1.0875x over previous
#include <cuda_runtime.h>
#include <math_constants.h>

#define SEQ  4096
#define HID  768
#define NB   8
#define KH   385   // HID/2 + 1 (Hermitian half + Nyquist)
#define AROWS 4

// ---------------------------------------------------------------- device state
__device__ float2 g_Y [NB * KH * SEQ];   // hidden-dim spectrum, [b][k][s]  (~101 MB)
__device__ float  g_Zr[NB * KH * SEQ];   // real 2D spectrum,    [b][k][m]  (~50 MB)
__device__ float2 g_w12[12 * 12];        // e^{-2pi i h1 k1 / 12}
__device__ float2 g_w768[768];           // e^{-2pi i p / 768}
__device__ float2 g_W64[64];             // e^{-2pi i p / 64}
__device__ float2 g_W4096[4096];         // e^{-2pi i p / 4096}

// ---------------------------------------------------------------- helpers
__device__ __forceinline__ float2 cadd(float2 a, float2 b){ return make_float2(a.x+b.x, a.y+b.y); }
__device__ __forceinline__ float2 csub(float2 a, float2 b){ return make_float2(a.x-b.x, a.y-b.y); }
__device__ __forceinline__ float2 mni (float2 a){ return make_float2(a.y, -a.x); }   // * (-i)
__device__ __forceinline__ float2 cmul(float2 a, float2 w){
    return make_float2(fmaf(a.x, w.x, -a.y * w.y), fmaf(a.x, w.y, a.y * w.x));
}
__device__ __forceinline__ int pad8(int p){ return p + (p >> 3); }

// 8-point DFT (negative exponent), in place. ~56 flops.
__device__ __forceinline__ void dft8(float2* v) {
    const float C = 0.70710678118654752f;
    float2 t0 = cadd(v[0], v[4]), t1 = csub(v[0], v[4]);
    float2 t2 = cadd(v[2], v[6]), t3 = csub(v[2], v[6]);
    float2 E0 = cadd(t0, t2), E2 = csub(t0, t2);
    float2 mt3 = mni(t3);
    float2 E1 = cadd(t1, mt3), E3 = csub(t1, mt3);
    float2 u0 = cadd(v[1], v[5]), u1 = csub(v[1], v[5]);
    float2 u2 = cadd(v[3], v[7]), u3 = csub(v[3], v[7]);
    float2 O0 = cadd(u0, u2), O2 = csub(u0, u2);
    float2 mu3 = mni(u3);
    float2 O1 = cadd(u1, mu3), O3 = csub(u1, mu3);
    float2 W1 = make_float2(C * (O1.x + O1.y), C * (O1.y - O1.x));   // W8^1 * O1
    float2 W2 = mni(O2);                                             // W8^2 * O2
    float2 W3 = make_float2(C * (O3.y - O3.x), -C * (O3.x + O3.y));  // W8^3 * O3
    v[0] = cadd(E0, O0);  v[4] = csub(E0, O0);
    v[1] = cadd(E1, W1);  v[5] = csub(E1, W1);
    v[2] = cadd(E2, W2);  v[6] = csub(E2, W2);
    v[3] = cadd(E3, W3);  v[7] = csub(E3, W3);
}

// One DIF radix-8 stage over 4096 points in padded smem.
template<int L, int TSH>
__device__ __forceinline__ void fft_stage(float2* sy, int t) {
    #pragma unroll
    for (int rep = 0; rep < 2; rep++) {
        int b = t + rep * 256;
        int blk = b / L, i = b - blk * L;
        int basep = blk * (8 * L) + i;
        float2 v[8];
        #pragma unroll
        for (int j = 0; j < 8; j++) v[j] = sy[pad8(basep + L * j)];
        dft8(v);
        #pragma unroll
        for (int k = 1; k < 8; k++) {        // i*k*TSH < 4096 always
            float2 w = __ldg(&g_W4096[i * k * TSH]);
            v[k] = cmul(v[k], w);
        }
        #pragma unroll
        for (int k = 0; k < 8; k++) sy[pad8(basep + L * k)] = v[k];
    }
}

// ---------------------------------------------------------------- init tables
__global__ void k_init() {
    int i = blockIdx.x * blockDim.x + threadIdx.x;
    if (i < 144) {
        int h1 = i / 12, r = i - h1 * 12;
        float s, c;
        sincospif(-2.0f * (float)(h1 * r) / 12.0f, &s, &c);
        g_w12[i] = make_float2(c, s);
    }
    if (i < 768) {
        float s, c;
        sincospif(-2.0f * (float)i / 768.0f, &s, &c);
        g_w768[i] = make_float2(c, s);
    }
    if (i < 64) {
        float s, c;
        sincospif(-(float)i / 32.0f, &s, &c);      // -2*pi*i/64
        g_W64[i] = make_float2(c, s);
    }
    if (i < 4096) {
        float s, c;
        sincospif(-(float)i / 2048.0f, &s, &c);    // -2*pi*i/4096
        g_W4096[i] = make_float2(c, s);
    }
}

// ------------------------------------------------- stage A: hidden-dim FFT(768)
// 768 = 12 x 64, n = h0 + 64 h1, k = k1 + 12 k2.
// T[h0][k1] = W768^{h0 k1} * sum_{h1<12} x[h0+64 h1] W12^{h1 k1}
// Y[k1+12 k2] = 64-pt FFT over h0 of T[.][k1]   (radix-8^2, digit-reversed out)
__global__ __launch_bounds__(256) void k_stageA(const float* __restrict__ x) {
    __shared__ float  sx[AROWS * HID];          // 12 KB
    __shared__ float2 sG[AROWS * 12 * 65];      // 24.96 KB, stride-65 padded
    int rowBase = blockIdx.x * AROWS;
    int b    = rowBase >> 12;
    int srow = rowBase & 4095;
    const float* xp = x + (size_t)rowBase * HID;
    int t = threadIdx.x;
    for (int i = t; i < AROWS * HID; i += 256) sx[i] = xp[i];
    __syncthreads();

    // 12-pt DFTs + fused W768 twiddle
    for (int e = t; e < AROWS * HID; e += 256) {
        int row = e / HID, idx = e - row * HID;
        int h0 = idx / 12, k1 = idx - h0 * 12;
        float gr = 0.f, gi = 0.f;
        #pragma unroll
        for (int h1 = 0; h1 < 12; h1++) {
            float v = sx[row * HID + h0 + 64 * h1];
            float2 w = __ldg(&g_w12[h1 * 12 + k1]);
            gr = fmaf(v, w.x, gr);
            gi = fmaf(v, w.y, gi);
        }
        float2 tw = __ldg(&g_w768[h0 * k1]);    // h0*k1 <= 693
        sG[(row * 12 + k1) * 65 + h0] = cmul(make_float2(gr, gi), tw);
    }
    __syncthreads();

    // 48 independent 64-pt FFTs (radix-8 DIF, 2 stages)
    for (int task = t; task < AROWS * 12 * 8; task += 256) {
        int f = task % (AROWS * 12), i = task / (AROWS * 12);   // i warp-uniform-ish
        float2* s = &sG[f * 65];
        float2 v[8];
        #pragma unroll
        for (int j = 0; j < 8; j++) v[j] = s[i + 8 * j];
        dft8(v);
        #pragma unroll
        for (int k = 1; k < 8; k++) v[k] = cmul(v[k], __ldg(&g_W64[i * k]));
        #pragma unroll
        for (int j = 0; j < 8; j++) s[i + 8 * j] = v[j];
    }
    __syncthreads();
    for (int task = t; task < AROWS * 12 * 8; task += 256) {
        int f = task % (AROWS * 12), blk = task / (AROWS * 12);
        float2* s = &sG[f * 65 + 8 * blk];
        float2 v[8];
        #pragma unroll
        for (int j = 0; j < 8; j++) v[j] = s[j];
        dft8(v);
        #pragma unroll
        for (int j = 0; j < 8; j++) s[j] = v[j];
    }
    __syncthreads();

    // write k = k1 + 12*k2 (k < KH); FFT slot p = base-8 digit reversal of k2
    for (int k = t; k < KH; k += 256) {
        int k2 = k / 12, k1 = k - k2 * 12;
        int p = ((k2 & 7) << 3) | (k2 >> 3);
        size_t o = ((size_t)(b * KH + k)) * SEQ + srow;
        #pragma unroll
        for (int row = 0; row < AROWS; row++)
            g_Y[o + row] = sG[(row * 12 + k1) * 65 + p];
    }
}

// --------------------------------------- stage B: seq-dim FFT(4096), radix-8^4
// (unchanged from R7 best)
__global__ __launch_bounds__(256) void k_stageB() {
    __shared__ float2 sy[SEQ + SEQ / 8];   // 36 KB, padded p+(p>>3)
    int col = blockIdx.x;                  // b*KH + k
    size_t base = (size_t)col * SEQ;
    int t = threadIdx.x;

    for (int n = t; n < SEQ; n += 256) sy[pad8(n)] = g_Y[base + n];
    __syncthreads();

    fft_stage<512, 1>(sy, t);  __syncthreads();
    fft_stage<64,  8>(sy, t);  __syncthreads();
    fft_stage<8,  64>(sy, t);  __syncthreads();

    float vx[16];
    int mb[2];
    #pragma unroll
    for (int rep = 0; rep < 2; rep++) {
        int b = t + rep * 256;
        float2 v[8];
        #pragma unroll
        for (int j = 0; j < 8; j++) v[j] = sy[pad8(8 * b + j)];
        dft8(v);
        int e0 = b & 7, e1 = (b >> 3) & 7, e2 = b >> 6;
        mb[rep] = e0 * 64 + e1 * 8 + e2;
        #pragma unroll
        for (int k = 0; k < 8; k++) vx[rep * 8 + k] = v[k].x;
    }
    __syncthreads();

    float* szr = (float*)sy;
    #pragma unroll
    for (int rep = 0; rep < 2; rep++)
        #pragma unroll
        for (int k = 0; k < 8; k++) {
            int m = k * 512 + mb[rep];
            szr[m + (m >> 6)] = vx[rep * 8 + k];
        }
    __syncthreads();

    for (int i = t; i < SEQ; i += 256)
        g_Zr[base + i] = szr[i + (i >> 6)];
}

// --------------------------------------- transpose + Hermitian mirror (unchanged)
__global__ __launch_bounds__(256) void k_trans(float* __restrict__ out) {
    __shared__ float tile[64][65];
    int t  = threadIdx.x;
    int b  = blockIdx.z;
    int k0 = blockIdx.y << 6;
    int m0 = blockIdx.x << 6;

    int mm  = t & 63, kkb = t >> 6;
    #pragma unroll 4
    for (int it = 0; it < 16; it++) {
        int kk = kkb + (it << 2);
        int k  = k0 + kk;
        int m  = m0 + mm;
        float v;
        if (k < KH) {
            v = g_Zr[((size_t)(b * KH + k)) * SEQ + m];
        } else {
            int ks = HID - k;
            int ms = (SEQ - m) & 4095;
            v = g_Zr[((size_t)(b * KH + ks)) * SEQ + ms];
        }
        tile[kk][mm] = v;
    }
    __syncthreads();

    int kk2 = t & 63, mmb = t >> 6;
    #pragma unroll 4
    for (int it = 0; it < 16; it++) {
        int mmw = mmb + (it << 2);
        out[((size_t)b * SEQ + m0 + mmw) * HID + k0 + kk2] = tile[kk2][mmw];
    }
}

extern "C" void kernel_launch(void* const* d_in, const int* in_sizes, int n_in,
                              void* d_out, int out_size) {
    (void)in_sizes; (void)n_in; (void)out_size;
    const float* x = (const float*)d_in[0];
    float* out = (float*)d_out;

    k_init   <<<16, 256>>>();
    k_stageA <<<NB * SEQ / AROWS, 256>>>(x);      // 8192 blocks
    k_stageB <<<NB * KH, 256>>>();                // 3080 blocks
    k_trans  <<<dim3(SEQ / 64, HID / 64, NB), 256>>>(out);   // 6144 blocks
}

// round 9
// speedup vs baseline: 2.7961x; 1.6626x over previous
#include <cuda_runtime.h>
#include <math_constants.h>

#define SEQ  4096
#define HID  768
#define NB   8
#define KH   385   // HID/2 + 1 (Hermitian half + Nyquist)
#define AROWS 4

// ---------------------------------------------------------------- device state
__device__ float2 g_Y [NB * KH * SEQ];   // hidden-dim spectrum, [b][k][s]  (~101 MB)
__device__ float  g_Zr[NB * KH * SEQ];   // real 2D spectrum,    [b][k][m]  (~50 MB)
__device__ float2 g_w12[12 * 12];        // e^{-2pi i h1 k1 / 12}
__device__ float2 g_w768[768];           // e^{-2pi i p / 768}
__device__ float2 g_W64[64];             // e^{-2pi i p / 64}
__device__ float2 g_W4096[4096];         // e^{-2pi i p / 4096}

// ---------------------------------------------------------------- helpers
__device__ __forceinline__ float2 cadd(float2 a, float2 b){ return make_float2(a.x+b.x, a.y+b.y); }
__device__ __forceinline__ float2 csub(float2 a, float2 b){ return make_float2(a.x-b.x, a.y-b.y); }
__device__ __forceinline__ float2 mni (float2 a){ return make_float2(a.y, -a.x); }   // * (-i)
__device__ __forceinline__ float2 cmul(float2 a, float2 w){
    return make_float2(fmaf(a.x, w.x, -a.y * w.y), fmaf(a.x, w.y, a.y * w.x));
}
__device__ __forceinline__ int pad8(int p){ return p + (p >> 3); }

// 8-point DFT (negative exponent), in place. ~56 flops.
__device__ __forceinline__ void dft8(float2* v) {
    const float C = 0.70710678118654752f;
    float2 t0 = cadd(v[0], v[4]), t1 = csub(v[0], v[4]);
    float2 t2 = cadd(v[2], v[6]), t3 = csub(v[2], v[6]);
    float2 E0 = cadd(t0, t2), E2 = csub(t0, t2);
    float2 mt3 = mni(t3);
    float2 E1 = cadd(t1, mt3), E3 = csub(t1, mt3);
    float2 u0 = cadd(v[1], v[5]), u1 = csub(v[1], v[5]);
    float2 u2 = cadd(v[3], v[7]), u3 = csub(v[3], v[7]);
    float2 O0 = cadd(u0, u2), O2 = csub(u0, u2);
    float2 mu3 = mni(u3);
    float2 O1 = cadd(u1, mu3), O3 = csub(u1, mu3);
    float2 W1 = make_float2(C * (O1.x + O1.y), C * (O1.y - O1.x));   // W8^1 * O1
    float2 W2 = mni(O2);                                             // W8^2 * O2
    float2 W3 = make_float2(C * (O3.y - O3.x), -C * (O3.x + O3.y));  // W8^3 * O3
    v[0] = cadd(E0, O0);  v[4] = csub(E0, O0);
    v[1] = cadd(E1, W1);  v[5] = csub(E1, W1);
    v[2] = cadd(E2, W2);  v[6] = csub(E2, W2);
    v[3] = cadd(E3, W3);  v[7] = csub(E3, W3);
}

// One DIF radix-8 stage over 4096 points in padded smem.
// Twiddles w^k generated from ONE coalesced LDG (w1 = W4096[i*TSH]) via
// register recurrence — no scattered L2 traffic (L1 is carved out by smem).
template<int L, int TSH>
__device__ __forceinline__ void fft_stage(float2* sy, int t) {
    #pragma unroll
    for (int rep = 0; rep < 2; rep++) {
        int b = t + rep * 256;
        int blk = b / L, i = b - blk * L;
        int basep = blk * (8 * L) + i;
        float2 w1 = __ldg(&g_W4096[i * TSH]);    // coalesced; hoisted over dft8
        float2 v[8];
        #pragma unroll
        for (int j = 0; j < 8; j++) v[j] = sy[pad8(basep + L * j)];
        dft8(v);
        float2 w = w1;
        v[1] = cmul(v[1], w);
        #pragma unroll
        for (int k = 2; k < 8; k++) {
            w = cmul(w, w1);                     // w = w1^k, unit modulus
            v[k] = cmul(v[k], w);
        }
        #pragma unroll
        for (int k = 0; k < 8; k++) sy[pad8(basep + L * k)] = v[k];
    }
}

// ---------------------------------------------------------------- init tables
__global__ void k_init() {
    int i = blockIdx.x * blockDim.x + threadIdx.x;
    if (i < 144) {
        int h1 = i / 12, r = i - h1 * 12;
        float s, c;
        sincospif(-2.0f * (float)(h1 * r) / 12.0f, &s, &c);
        g_w12[i] = make_float2(c, s);
    }
    if (i < 768) {
        float s, c;
        sincospif(-2.0f * (float)i / 768.0f, &s, &c);
        g_w768[i] = make_float2(c, s);
    }
    if (i < 64) {
        float s, c;
        sincospif(-(float)i / 32.0f, &s, &c);      // -2*pi*i/64
        g_W64[i] = make_float2(c, s);
    }
    if (i < 4096) {
        float s, c;
        sincospif(-(float)i / 2048.0f, &s, &c);    // -2*pi*i/4096
        g_W4096[i] = make_float2(c, s);
    }
}

// ------------------------------------------------- stage A: hidden-dim FFT(768)
// (unchanged from R8 best)
__global__ __launch_bounds__(256) void k_stageA(const float* __restrict__ x) {
    __shared__ float  sx[AROWS * HID];          // 12 KB
    __shared__ float2 sG[AROWS * 12 * 65];      // 24.96 KB, stride-65 padded
    int rowBase = blockIdx.x * AROWS;
    int b    = rowBase >> 12;
    int srow = rowBase & 4095;
    const float* xp = x + (size_t)rowBase * HID;
    int t = threadIdx.x;
    for (int i = t; i < AROWS * HID; i += 256) sx[i] = xp[i];
    __syncthreads();

    // 12-pt DFTs + fused W768 twiddle
    for (int e = t; e < AROWS * HID; e += 256) {
        int row = e / HID, idx = e - row * HID;
        int h0 = idx / 12, k1 = idx - h0 * 12;
        float gr = 0.f, gi = 0.f;
        #pragma unroll
        for (int h1 = 0; h1 < 12; h1++) {
            float v = sx[row * HID + h0 + 64 * h1];
            float2 w = __ldg(&g_w12[h1 * 12 + k1]);
            gr = fmaf(v, w.x, gr);
            gi = fmaf(v, w.y, gi);
        }
        float2 tw = __ldg(&g_w768[h0 * k1]);    // h0*k1 <= 693
        sG[(row * 12 + k1) * 65 + h0] = cmul(make_float2(gr, gi), tw);
    }
    __syncthreads();

    // 48 independent 64-pt FFTs (radix-8 DIF, 2 stages)
    for (int task = t; task < AROWS * 12 * 8; task += 256) {
        int f = task % (AROWS * 12), i = task / (AROWS * 12);
        float2* s = &sG[f * 65];
        float2 v[8];
        #pragma unroll
        for (int j = 0; j < 8; j++) v[j] = s[i + 8 * j];
        dft8(v);
        #pragma unroll
        for (int k = 1; k < 8; k++) v[k] = cmul(v[k], __ldg(&g_W64[i * k]));
        #pragma unroll
        for (int j = 0; j < 8; j++) s[i + 8 * j] = v[j];
    }
    __syncthreads();
    for (int task = t; task < AROWS * 12 * 8; task += 256) {
        int f = task % (AROWS * 12), blk = task / (AROWS * 12);
        float2* s = &sG[f * 65 + 8 * blk];
        float2 v[8];
        #pragma unroll
        for (int j = 0; j < 8; j++) v[j] = s[j];
        dft8(v);
        #pragma unroll
        for (int j = 0; j < 8; j++) s[j] = v[j];
    }
    __syncthreads();

    // write k = k1 + 12*k2 (k < KH); FFT slot p = base-8 digit reversal of k2
    for (int k = t; k < KH; k += 256) {
        int k2 = k / 12, k1 = k - k2 * 12;
        int p = ((k2 & 7) << 3) | (k2 >> 3);
        size_t o = ((size_t)(b * KH + k)) * SEQ + srow;
        #pragma unroll
        for (int row = 0; row < AROWS; row++)
            g_Y[o + row] = sG[(row * 12 + k1) * 65 + p];
    }
}

// --------------------------------------- stage B: seq-dim FFT(4096), radix-8^4
// One (b,k) column per block; recurrence twiddles (see fft_stage).
__global__ __launch_bounds__(256) void k_stageB() {
    __shared__ float2 sy[SEQ + SEQ / 8];   // 36 KB, padded p+(p>>3)
    int col = blockIdx.x;                  // b*KH + k
    size_t base = (size_t)col * SEQ;
    int t = threadIdx.x;

    for (int n = t; n < SEQ; n += 256) sy[pad8(n)] = g_Y[base + n];
    __syncthreads();

    fft_stage<512, 1>(sy, t);  __syncthreads();
    fft_stage<64,  8>(sy, t);  __syncthreads();
    fft_stage<8,  64>(sy, t);  __syncthreads();

    float vx[16];
    int mb[2];
    #pragma unroll
    for (int rep = 0; rep < 2; rep++) {
        int b = t + rep * 256;
        float2 v[8];
        #pragma unroll
        for (int j = 0; j < 8; j++) v[j] = sy[pad8(8 * b + j)];
        dft8(v);
        int e0 = b & 7, e1 = (b >> 3) & 7, e2 = b >> 6;
        mb[rep] = e0 * 64 + e1 * 8 + e2;
        #pragma unroll
        for (int k = 0; k < 8; k++) vx[rep * 8 + k] = v[k].x;
    }
    __syncthreads();

    float* szr = (float*)sy;
    #pragma unroll
    for (int rep = 0; rep < 2; rep++)
        #pragma unroll
        for (int k = 0; k < 8; k++) {
            int m = k * 512 + mb[rep];
            szr[m + (m >> 6)] = vx[rep * 8 + k];
        }
    __syncthreads();

    for (int i = t; i < SEQ; i += 256)
        g_Zr[base + i] = szr[i + (i >> 6)];
}

// --------------------------------------- transpose + Hermitian mirror (unchanged)
__global__ __launch_bounds__(256) void k_trans(float* __restrict__ out) {
    __shared__ float tile[64][65];
    int t  = threadIdx.x;
    int b  = blockIdx.z;
    int k0 = blockIdx.y << 6;
    int m0 = blockIdx.x << 6;

    int mm  = t & 63, kkb = t >> 6;
    #pragma unroll 4
    for (int it = 0; it < 16; it++) {
        int kk = kkb + (it << 2);
        int k  = k0 + kk;
        int m  = m0 + mm;
        float v;
        if (k < KH) {
            v = g_Zr[((size_t)(b * KH + k)) * SEQ + m];
        } else {
            int ks = HID - k;
            int ms = (SEQ - m) & 4095;
            v = g_Zr[((size_t)(b * KH + ks)) * SEQ + ms];
        }
        tile[kk][mm] = v;
    }
    __syncthreads();

    int kk2 = t & 63, mmb = t >> 6;
    #pragma unroll 4
    for (int it = 0; it < 16; it++) {
        int mmw = mmb + (it << 2);
        out[((size_t)b * SEQ + m0 + mmw) * HID + k0 + kk2] = tile[kk2][mmw];
    }
}

extern "C" void kernel_launch(void* const* d_in, const int* in_sizes, int n_in,
                              void* d_out, int out_size) {
    (void)in_sizes; (void)n_in; (void)out_size;
    const float* x = (const float*)d_in[0];
    float* out = (float*)d_out;

    k_init   <<<16, 256>>>();
    k_stageA <<<NB * SEQ / AROWS, 256>>>(x);      // 8192 blocks
    k_stageB <<<NB * KH, 256>>>();                // 3080 blocks
    k_trans  <<<dim3(SEQ / 64, HID / 64, NB), 256>>>(out);   // 6144 blocks
}

// round 10
// speedup vs baseline: 2.8809x; 1.0303x over previous
#include <cuda_runtime.h>
#include <math_constants.h>

#define SEQ  4096
#define HID  768
#define NB   8
#define KH   385   // HID/2 + 1 (Hermitian half + Nyquist)
#define AROWS 4

// ---------------------------------------------------------------- device state
__device__ float2 g_Y [NB * KH * SEQ];   // hidden-dim spectrum, [b][k][s]  (~101 MB)
__device__ float  g_Zr[NB * KH * SEQ];   // real 2D spectrum,    [b][k][m]  (~50 MB)
__device__ float2 g_w12[12 * 12];        // e^{-2pi i h1 k1 / 12}
__device__ float2 g_w768[768];           // e^{-2pi i p / 768}
__device__ float2 g_W64[64];             // e^{-2pi i p / 64}
__device__ float2 g_W4096[4096];         // e^{-2pi i p / 4096}

// ---------------------------------------------------------------- helpers
__device__ __forceinline__ float2 cadd(float2 a, float2 b){ return make_float2(a.x+b.x, a.y+b.y); }
__device__ __forceinline__ float2 csub(float2 a, float2 b){ return make_float2(a.x-b.x, a.y-b.y); }
__device__ __forceinline__ float2 mni (float2 a){ return make_float2(a.y, -a.x); }   // * (-i)
__device__ __forceinline__ float2 cmul(float2 a, float2 w){
    return make_float2(fmaf(a.x, w.x, -a.y * w.y), fmaf(a.x, w.y, a.y * w.x));
}
__device__ __forceinline__ int pad8(int p){ return p + (p >> 3); }

// 8-point DFT (negative exponent), in place. ~56 flops.
__device__ __forceinline__ void dft8(float2* v) {
    const float C = 0.70710678118654752f;
    float2 t0 = cadd(v[0], v[4]), t1 = csub(v[0], v[4]);
    float2 t2 = cadd(v[2], v[6]), t3 = csub(v[2], v[6]);
    float2 E0 = cadd(t0, t2), E2 = csub(t0, t2);
    float2 mt3 = mni(t3);
    float2 E1 = cadd(t1, mt3), E3 = csub(t1, mt3);
    float2 u0 = cadd(v[1], v[5]), u1 = csub(v[1], v[5]);
    float2 u2 = cadd(v[3], v[7]), u3 = csub(v[3], v[7]);
    float2 O0 = cadd(u0, u2), O2 = csub(u0, u2);
    float2 mu3 = mni(u3);
    float2 O1 = cadd(u1, mu3), O3 = csub(u1, mu3);
    float2 W1 = make_float2(C * (O1.x + O1.y), C * (O1.y - O1.x));   // W8^1 * O1
    float2 W2 = mni(O2);                                             // W8^2 * O2
    float2 W3 = make_float2(C * (O3.y - O3.x), -C * (O3.x + O3.y));  // W8^3 * O3
    v[0] = cadd(E0, O0);  v[4] = csub(E0, O0);
    v[1] = cadd(E1, W1);  v[5] = csub(E1, W1);
    v[2] = cadd(E2, W2);  v[6] = csub(E2, W2);
    v[3] = cadd(E3, W3);  v[7] = csub(E3, W3);
}

// One DIF radix-8 stage over 4096 points in padded smem.
// Twiddles w^k generated from ONE coalesced LDG (w1 = W4096[i*TSH]) via
// register recurrence — no scattered L2 traffic (L1 is carved out by smem).
template<int L, int TSH>
__device__ __forceinline__ void fft_stage(float2* sy, int t) {
    #pragma unroll
    for (int rep = 0; rep < 2; rep++) {
        int b = t + rep * 256;
        int blk = b / L, i = b - blk * L;
        int basep = blk * (8 * L) + i;
        float2 w1 = __ldg(&g_W4096[i * TSH]);    // coalesced; hoisted over dft8
        float2 v[8];
        #pragma unroll
        for (int j = 0; j < 8; j++) v[j] = sy[pad8(basep + L * j)];
        dft8(v);
        float2 w = w1;
        v[1] = cmul(v[1], w);
        #pragma unroll
        for (int k = 2; k < 8; k++) {
            w = cmul(w, w1);                     // w = w1^k, unit modulus
            v[k] = cmul(v[k], w);
        }
        #pragma unroll
        for (int k = 0; k < 8; k++) sy[pad8(basep + L * k)] = v[k];
    }
}

// ---------------------------------------------------------------- init tables
__global__ void k_init() {
    int i = blockIdx.x * blockDim.x + threadIdx.x;
    if (i < 144) {
        int h1 = i / 12, r = i - h1 * 12;
        float s, c;
        sincospif(-2.0f * (float)(h1 * r) / 12.0f, &s, &c);
        g_w12[i] = make_float2(c, s);
    }
    if (i < 768) {
        float s, c;
        sincospif(-2.0f * (float)i / 768.0f, &s, &c);
        g_w768[i] = make_float2(c, s);
    }
    if (i < 64) {
        float s, c;
        sincospif(-(float)i / 32.0f, &s, &c);      // -2*pi*i/64
        g_W64[i] = make_float2(c, s);
    }
    if (i < 4096) {
        float s, c;
        sincospif(-(float)i / 2048.0f, &s, &c);    // -2*pi*i/4096
        g_W4096[i] = make_float2(c, s);
    }
}

// ------------------------------------------------- stage A: hidden-dim FFT(768)
// 768 = 12 x 64, n = h0 + 64 h1, k = k1 + 12 k2.
// All twiddle tables staged in smem: carveout leaves ~6 KB of L1, so the
// per-element scattered table LDGs were going to L2 (same bug R9 fixed in B).
__global__ __launch_bounds__(256) void k_stageA(const float* __restrict__ x) {
    __shared__ float  sx[AROWS * HID];          // 12 KB
    __shared__ float2 sG[AROWS * 12 * 65];      // 24.96 KB, stride-65 padded
    __shared__ float2 sw768[768];               // 6 KB
    __shared__ float2 sw12[144];                // 1.125 KB
    __shared__ float2 sw64[64];                 // 0.5 KB
    int rowBase = blockIdx.x * AROWS;
    int b    = rowBase >> 12;
    int srow = rowBase & 4095;
    const float* xp = x + (size_t)rowBase * HID;
    int t = threadIdx.x;
    for (int i = t; i < AROWS * HID; i += 256) sx[i] = xp[i];
    for (int i = t; i < 768; i += 256) sw768[i] = g_w768[i];
    if (t < 144) sw12[t] = g_w12[t];
    int tt = t - 192;
    if (tt >= 0 && tt < 64) sw64[tt] = g_W64[tt];
    __syncthreads();

    // 12-pt DFTs + fused W768 twiddle (tables now LDS broadcasts)
    for (int e = t; e < AROWS * HID; e += 256) {
        int row = e / HID, idx = e - row * HID;
        int h0 = idx / 12, k1 = idx - h0 * 12;
        float gr = 0.f, gi = 0.f;
        #pragma unroll
        for (int h1 = 0; h1 < 12; h1++) {
            float v = sx[row * HID + h0 + 64 * h1];
            float2 w = sw12[h1 * 12 + k1];
            gr = fmaf(v, w.x, gr);
            gi = fmaf(v, w.y, gi);
        }
        float2 tw = sw768[h0 * k1];             // h0*k1 <= 693
        sG[(row * 12 + k1) * 65 + h0] = cmul(make_float2(gr, gi), tw);
    }
    __syncthreads();

    // 48 independent 64-pt FFTs (radix-8 DIF, 2 stages)
    for (int task = t; task < AROWS * 12 * 8; task += 256) {
        int f = task % (AROWS * 12), i = task / (AROWS * 12);
        float2* s = &sG[f * 65];
        float2 v[8];
        #pragma unroll
        for (int j = 0; j < 8; j++) v[j] = s[i + 8 * j];
        dft8(v);
        #pragma unroll
        for (int k = 1; k < 8; k++) v[k] = cmul(v[k], sw64[i * k]);
        #pragma unroll
        for (int j = 0; j < 8; j++) s[i + 8 * j] = v[j];
    }
    __syncthreads();
    for (int task = t; task < AROWS * 12 * 8; task += 256) {
        int f = task % (AROWS * 12), blk = task / (AROWS * 12);
        float2* s = &sG[f * 65 + 8 * blk];
        float2 v[8];
        #pragma unroll
        for (int j = 0; j < 8; j++) v[j] = s[j];
        dft8(v);
        #pragma unroll
        for (int j = 0; j < 8; j++) s[j] = v[j];
    }
    __syncthreads();

    // write k = k1 + 12*k2 (k < KH); FFT slot p = base-8 digit reversal of k2
    for (int k = t; k < KH; k += 256) {
        int k2 = k / 12, k1 = k - k2 * 12;
        int p = ((k2 & 7) << 3) | (k2 >> 3);
        size_t o = ((size_t)(b * KH + k)) * SEQ + srow;
        #pragma unroll
        for (int row = 0; row < AROWS; row++)
            g_Y[o + row] = sG[(row * 12 + k1) * 65 + p];
    }
}

// --------------------------------------- stage B: seq-dim FFT(4096), radix-8^4
// (unchanged from R9 best)
__global__ __launch_bounds__(256) void k_stageB() {
    __shared__ float2 sy[SEQ + SEQ / 8];   // 36 KB, padded p+(p>>3)
    int col = blockIdx.x;                  // b*KH + k
    size_t base = (size_t)col * SEQ;
    int t = threadIdx.x;

    for (int n = t; n < SEQ; n += 256) sy[pad8(n)] = g_Y[base + n];
    __syncthreads();

    fft_stage<512, 1>(sy, t);  __syncthreads();
    fft_stage<64,  8>(sy, t);  __syncthreads();
    fft_stage<8,  64>(sy, t);  __syncthreads();

    float vx[16];
    int mb[2];
    #pragma unroll
    for (int rep = 0; rep < 2; rep++) {
        int b = t + rep * 256;
        float2 v[8];
        #pragma unroll
        for (int j = 0; j < 8; j++) v[j] = sy[pad8(8 * b + j)];
        dft8(v);
        int e0 = b & 7, e1 = (b >> 3) & 7, e2 = b >> 6;
        mb[rep] = e0 * 64 + e1 * 8 + e2;
        #pragma unroll
        for (int k = 0; k < 8; k++) vx[rep * 8 + k] = v[k].x;
    }
    __syncthreads();

    float* szr = (float*)sy;
    #pragma unroll
    for (int rep = 0; rep < 2; rep++)
        #pragma unroll
        for (int k = 0; k < 8; k++) {
            int m = k * 512 + mb[rep];
            szr[m + (m >> 6)] = vx[rep * 8 + k];
        }
    __syncthreads();

    for (int i = t; i < SEQ; i += 256)
        g_Zr[base + i] = szr[i + (i >> 6)];
}

// --------------------------------------- transpose + Hermitian mirror (unchanged)
__global__ __launch_bounds__(256) void k_trans(float* __restrict__ out) {
    __shared__ float tile[64][65];
    int t  = threadIdx.x;
    int b  = blockIdx.z;
    int k0 = blockIdx.y << 6;
    int m0 = blockIdx.x << 6;

    int mm  = t & 63, kkb = t >> 6;
    #pragma unroll 4
    for (int it = 0; it < 16; it++) {
        int kk = kkb + (it << 2);
        int k  = k0 + kk;
        int m  = m0 + mm;
        float v;
        if (k < KH) {
            v = g_Zr[((size_t)(b * KH + k)) * SEQ + m];
        } else {
            int ks = HID - k;
            int ms = (SEQ - m) & 4095;
            v = g_Zr[((size_t)(b * KH + ks)) * SEQ + ms];
        }
        tile[kk][mm] = v;
    }
    __syncthreads();

    int kk2 = t & 63, mmb = t >> 6;
    #pragma unroll 4
    for (int it = 0; it < 16; it++) {
        int mmw = mmb + (it << 2);
        out[((size_t)b * SEQ + m0 + mmw) * HID + k0 + kk2] = tile[kk2][mmw];
    }
}

extern "C" void kernel_launch(void* const* d_in, const int* in_sizes, int n_in,
                              void* d_out, int out_size) {
    (void)in_sizes; (void)n_in; (void)out_size;
    const float* x = (const float*)d_in[0];
    float* out = (float*)d_out;

    k_init   <<<16, 256>>>();
    k_stageA <<<NB * SEQ / AROWS, 256>>>(x);      // 8192 blocks
    k_stageB <<<NB * KH, 256>>>();                // 3080 blocks
    k_trans  <<<dim3(SEQ / 64, HID / 64, NB), 256>>>(out);   // 6144 blocks
}

// round 11
// speedup vs baseline: 3.7287x; 1.2943x over previous
#include <cuda_runtime.h>
#include <math_constants.h>

#define SEQ  4096
#define HID  768
#define NB   8
#define KH   385   // HID/2 + 1 (Hermitian half + Nyquist)
#define AROWS 4
#define KT   32    // k-tile width for B1/B2
#define NKT  13    // ceil(385/32)

// ---------------------------------------------------------------- device state
__device__ float2 g_Y [NB * SEQ * KH];        // A out:  [b][s][k]   (~101 MB)
__device__ float2 g_Y2[NB * 64 * 64 * KH];    // B1 out: [b][m0][s0][k] (~101 MB)
__device__ float2 g_w12[12 * 12];             // e^{-2pi i h1 k1 / 12}
__device__ float2 g_w768[768];                // e^{-2pi i p / 768}
__device__ float2 g_W64[64];                  // e^{-2pi i p / 64}
__device__ float2 g_W4096[4096];              // e^{-2pi i p / 4096}

// ---------------------------------------------------------------- helpers
__device__ __forceinline__ float2 cadd(float2 a, float2 b){ return make_float2(a.x+b.x, a.y+b.y); }
__device__ __forceinline__ float2 csub(float2 a, float2 b){ return make_float2(a.x-b.x, a.y-b.y); }
__device__ __forceinline__ float2 mni (float2 a){ return make_float2(a.y, -a.x); }   // * (-i)
__device__ __forceinline__ float2 cmul(float2 a, float2 w){
    return make_float2(fmaf(a.x, w.x, -a.y * w.y), fmaf(a.x, w.y, a.y * w.x));
}
__device__ __forceinline__ int rev8x8(int m){ return ((m & 7) << 3) | (m >> 3); }

// 8-point DFT (negative exponent), in place. ~56 flops.
__device__ __forceinline__ void dft8(float2* v) {
    const float C = 0.70710678118654752f;
    float2 t0 = cadd(v[0], v[4]), t1 = csub(v[0], v[4]);
    float2 t2 = cadd(v[2], v[6]), t3 = csub(v[2], v[6]);
    float2 E0 = cadd(t0, t2), E2 = csub(t0, t2);
    float2 mt3 = mni(t3);
    float2 E1 = cadd(t1, mt3), E3 = csub(t1, mt3);
    float2 u0 = cadd(v[1], v[5]), u1 = csub(v[1], v[5]);
    float2 u2 = cadd(v[3], v[7]), u3 = csub(v[3], v[7]);
    float2 O0 = cadd(u0, u2), O2 = csub(u0, u2);
    float2 mu3 = mni(u3);
    float2 O1 = cadd(u1, mu3), O3 = csub(u1, mu3);
    float2 W1 = make_float2(C * (O1.x + O1.y), C * (O1.y - O1.x));   // W8^1 * O1
    float2 W2 = mni(O2);                                             // W8^2 * O2
    float2 W3 = make_float2(C * (O3.y - O3.x), -C * (O3.x + O3.y));  // W8^3 * O3
    v[0] = cadd(E0, O0);  v[4] = csub(E0, O0);
    v[1] = cadd(E1, W1);  v[5] = csub(E1, W1);
    v[2] = cadd(E2, W2);  v[6] = csub(E2, W2);
    v[3] = cadd(E3, W3);  v[7] = csub(E3, W3);
}

// Two-stage radix-8 64-pt FFT on a [64][KT] smem tile, along dim0, thread
// owns (kk = t&31, r0 = t>>5). All accesses are row-contiguous -> conflict-free.
// Output is digit-reversed: X[m] lives in row rev8x8(m).
__device__ __forceinline__ void fft64_tile(float2* tile, int kk, int r0) {
    {   // stage 1: butterflies over stride 8, twiddle W64^{i*k}
        int i = r0;
        float2 v[8];
        #pragma unroll
        for (int j = 0; j < 8; j++) v[j] = tile[(i + 8 * j) * KT + kk];
        dft8(v);
        #pragma unroll
        for (int k = 1; k < 8; k++) v[k] = cmul(v[k], __ldg(&g_W64[i * k]));
        #pragma unroll
        for (int j = 0; j < 8; j++) tile[(i + 8 * j) * KT + kk] = v[j];
    }
    __syncthreads();
    {   // stage 2: contiguous groups of 8
        float2 v[8];
        #pragma unroll
        for (int j = 0; j < 8; j++) v[j] = tile[(8 * r0 + j) * KT + kk];
        dft8(v);
        #pragma unroll
        for (int j = 0; j < 8; j++) tile[(8 * r0 + j) * KT + kk] = v[j];
    }
    __syncthreads();
}

// ---------------------------------------------------------------- init tables
__global__ void k_init() {
    int i = blockIdx.x * blockDim.x + threadIdx.x;
    if (i < 144) {
        int h1 = i / 12, r = i - h1 * 12;
        float s, c;
        sincospif(-2.0f * (float)(h1 * r) / 12.0f, &s, &c);
        g_w12[i] = make_float2(c, s);
    }
    if (i < 768) {
        float s, c;
        sincospif(-2.0f * (float)i / 768.0f, &s, &c);
        g_w768[i] = make_float2(c, s);
    }
    if (i < 64) {
        float s, c;
        sincospif(-(float)i / 32.0f, &s, &c);      // -2*pi*i/64
        g_W64[i] = make_float2(c, s);
    }
    if (i < 4096) {
        float s, c;
        sincospif(-(float)i / 2048.0f, &s, &c);    // -2*pi*i/4096
        g_W4096[i] = make_float2(c, s);
    }
}

// ------------------------------------------------- stage A: hidden-dim FFT(768)
// 768 = 12 x 64. Same verified compute as R10; epilogue now writes the
// NATURAL layout g_Y[b][s][k] -> fully coalesced (no more 32B sector scatter).
__global__ __launch_bounds__(256) void k_stageA(const float* __restrict__ x) {
    __shared__ float  sx[AROWS * HID];          // 12 KB
    __shared__ float2 sG[AROWS * 12 * 65];      // 24.96 KB, stride-65 padded
    __shared__ float2 sw768[768];               // 6 KB
    __shared__ float2 sw12[144];
    __shared__ float2 sw64[64];
    int rowBase = blockIdx.x * AROWS;
    int b    = rowBase >> 12;
    int srow = rowBase & 4095;
    const float* xp = x + (size_t)rowBase * HID;
    int t = threadIdx.x;
    for (int i = t; i < AROWS * HID; i += 256) sx[i] = xp[i];
    for (int i = t; i < 768; i += 256) sw768[i] = g_w768[i];
    if (t < 144) sw12[t] = g_w12[t];
    int tt = t - 192;
    if (tt >= 0 && tt < 64) sw64[tt] = g_W64[tt];
    __syncthreads();

    // 12-pt DFTs + fused W768 twiddle
    for (int e = t; e < AROWS * HID; e += 256) {
        int row = e / HID, idx = e - row * HID;
        int h0 = idx / 12, k1 = idx - h0 * 12;
        float gr = 0.f, gi = 0.f;
        #pragma unroll
        for (int h1 = 0; h1 < 12; h1++) {
            float v = sx[row * HID + h0 + 64 * h1];
            float2 w = sw12[h1 * 12 + k1];
            gr = fmaf(v, w.x, gr);
            gi = fmaf(v, w.y, gi);
        }
        float2 tw = sw768[h0 * k1];             // h0*k1 <= 693
        sG[(row * 12 + k1) * 65 + h0] = cmul(make_float2(gr, gi), tw);
    }
    __syncthreads();

    // 48 independent 64-pt FFTs (radix-8 DIF, 2 stages)
    for (int task = t; task < AROWS * 12 * 8; task += 256) {
        int f = task % (AROWS * 12), i = task / (AROWS * 12);
        float2* s = &sG[f * 65];
        float2 v[8];
        #pragma unroll
        for (int j = 0; j < 8; j++) v[j] = s[i + 8 * j];
        dft8(v);
        #pragma unroll
        for (int k = 1; k < 8; k++) v[k] = cmul(v[k], sw64[i * k]);
        #pragma unroll
        for (int j = 0; j < 8; j++) s[i + 8 * j] = v[j];
    }
    __syncthreads();
    for (int task = t; task < AROWS * 12 * 8; task += 256) {
        int f = task % (AROWS * 12), blk = task / (AROWS * 12);
        float2* s = &sG[f * 65 + 8 * blk];
        float2 v[8];
        #pragma unroll
        for (int j = 0; j < 8; j++) v[j] = s[j];
        dft8(v);
        #pragma unroll
        for (int j = 0; j < 8; j++) s[j] = v[j];
    }
    __syncthreads();

    // write k = k1 + 12*k2 (k < KH) to g_Y[b][s][k]; slot p = rev(k2)
    for (int k = t; k < KH; k += 256) {
        int k2 = k / 12, k1 = k - k2 * 12;
        int p = rev8x8(k2);
        #pragma unroll
        for (int row = 0; row < AROWS; row++)
            g_Y[((size_t)(b * SEQ) + srow + row) * KH + k] =
                sG[(row * 12 + k1) * 65 + p];
    }
}

// --------------------------------------- B1: seq FFT step 1 (over s1) + twiddle
// block (ktile, s0, b): A1[m0] = W4096^{s0 m0} * sum_{s1} Y[s0+64 s1][k] W64^{s1 m0}
// -> g_Y2[b][m0][s0][k]
__global__ __launch_bounds__(256) void k_B1() {
    __shared__ float2 tile[64 * KT];   // 16 KB
    int k0 = blockIdx.x * KT;
    int s0 = blockIdx.y;
    int b  = blockIdx.z;
    int t  = threadIdx.x;
    int kk = t & 31, r0 = t >> 5;
    int k  = k0 + kk;
    bool ok = (k < KH);

    #pragma unroll
    for (int j = 0; j < 8; j++) {
        int s1 = r0 + 8 * j;
        tile[s1 * KT + kk] = ok ?
            g_Y[((size_t)(b * SEQ) + s0 + 64 * s1) * KH + k] : make_float2(0.f, 0.f);
    }
    __syncthreads();

    fft64_tile(tile, kk, r0);

    #pragma unroll
    for (int m0b = 0; m0b < 64; m0b += 8) {
        int m0 = m0b + r0;
        float2 v = tile[rev8x8(m0) * KT + kk];
        float2 w = __ldg(&g_W4096[s0 * m0]);         // warp-uniform broadcast
        v = cmul(v, w);
        if (ok)
            g_Y2[(((size_t)b * 64 + m0) * 64 + s0) * KH + k] = v;
    }
}

// --------------------------------------- B2: seq FFT step 2 (over s0), real part,
// writes out[b][m][k] for k<385 AND the Hermitian mirror out[b][(4096-m)%4096][768-k]
// for k in 1..383. Every out element written exactly once; all stores coalesced.
__global__ __launch_bounds__(256) void k_B2(float* __restrict__ out) {
    __shared__ float2 tile[64 * KT];   // 16 KB
    int k0 = blockIdx.x * KT;
    int m0 = blockIdx.y;
    int b  = blockIdx.z;
    int t  = threadIdx.x;
    int kk = t & 31, r0 = t >> 5;
    int k  = k0 + kk;
    bool ok = (k < KH);

    #pragma unroll
    for (int j = 0; j < 8; j++) {
        int s0 = r0 + 8 * j;
        tile[s0 * KT + kk] = ok ?
            g_Y2[(((size_t)b * 64 + m0) * 64 + s0) * KH + k] : make_float2(0.f, 0.f);
    }
    __syncthreads();

    fft64_tile(tile, kk, r0);

    bool domir = (k >= 1 && k <= 383);
    #pragma unroll
    for (int m1b = 0; m1b < 64; m1b += 8) {
        int m1 = m1b + r0;
        float zr = tile[rev8x8(m1) * KT + kk].x;
        int m = m0 + 64 * m1;
        if (ok)
            out[((size_t)b * SEQ + m) * HID + k] = zr;
        if (domir) {
            int mp = (SEQ - m) & 4095;
            out[((size_t)b * SEQ + mp) * HID + (HID - k)] = zr;
        }
    }
}

extern "C" void kernel_launch(void* const* d_in, const int* in_sizes, int n_in,
                              void* d_out, int out_size) {
    (void)in_sizes; (void)n_in; (void)out_size;
    const float* x = (const float*)d_in[0];
    float* out = (float*)d_out;

    k_init   <<<16, 256>>>();
    k_stageA <<<NB * SEQ / AROWS, 256>>>(x);        // 8192 blocks
    k_B1     <<<dim3(NKT, 64, NB), 256>>>();        // 6656 blocks
    k_B2     <<<dim3(NKT, 64, NB), 256>>>(out);     // 6656 blocks
}

// round 12
// speedup vs baseline: 5.2326x; 1.4034x over previous
#include <cuda_runtime.h>
#include <math_constants.h>

#define SEQ  4096
#define HID  768
#define NB   8
#define KH   385   // HID/2 + 1 (Hermitian half + Nyquist)
#define AROWS 4    // real rows per block -> 2 complex FFTs (pair trick)
#define KT   32    // k-tile width for B1/B2
#define NKT  13    // ceil(385/32)

// ---------------------------------------------------------------- device state
__device__ float2 g_Y [NB * SEQ * KH];        // A out:  [b][s][k]   (~101 MB)
__device__ float2 g_Y2[NB * 64 * 64 * KH];    // B1 out: [b][m0][s0][k] (~101 MB)
__device__ float2 g_w12[12 * 12];             // e^{-2pi i h1 k1 / 12}
__device__ float2 g_w768[768];                // e^{-2pi i p / 768}
__device__ float2 g_W64[64];                  // e^{-2pi i p / 64}
__device__ float2 g_W4096[4096];              // e^{-2pi i p / 4096}

// ---------------------------------------------------------------- helpers
__device__ __forceinline__ float2 cadd(float2 a, float2 b){ return make_float2(a.x+b.x, a.y+b.y); }
__device__ __forceinline__ float2 csub(float2 a, float2 b){ return make_float2(a.x-b.x, a.y-b.y); }
__device__ __forceinline__ float2 mni (float2 a){ return make_float2(a.y, -a.x); }   // * (-i)
__device__ __forceinline__ float2 cmul(float2 a, float2 w){
    return make_float2(fmaf(a.x, w.x, -a.y * w.y), fmaf(a.x, w.y, a.y * w.x));
}
__device__ __forceinline__ int rev8x8(int m){ return ((m & 7) << 3) | (m >> 3); }

// 8-point DFT (negative exponent), in place. ~56 flops.
__device__ __forceinline__ void dft8(float2* v) {
    const float C = 0.70710678118654752f;
    float2 t0 = cadd(v[0], v[4]), t1 = csub(v[0], v[4]);
    float2 t2 = cadd(v[2], v[6]), t3 = csub(v[2], v[6]);
    float2 E0 = cadd(t0, t2), E2 = csub(t0, t2);
    float2 mt3 = mni(t3);
    float2 E1 = cadd(t1, mt3), E3 = csub(t1, mt3);
    float2 u0 = cadd(v[1], v[5]), u1 = csub(v[1], v[5]);
    float2 u2 = cadd(v[3], v[7]), u3 = csub(v[3], v[7]);
    float2 O0 = cadd(u0, u2), O2 = csub(u0, u2);
    float2 mu3 = mni(u3);
    float2 O1 = cadd(u1, mu3), O3 = csub(u1, mu3);
    float2 W1 = make_float2(C * (O1.x + O1.y), C * (O1.y - O1.x));   // W8^1 * O1
    float2 W2 = mni(O2);                                             // W8^2 * O2
    float2 W3 = make_float2(C * (O3.y - O3.x), -C * (O3.x + O3.y));  // W8^3 * O3
    v[0] = cadd(E0, O0);  v[4] = csub(E0, O0);
    v[1] = cadd(E1, W1);  v[5] = csub(E1, W1);
    v[2] = cadd(E2, W2);  v[6] = csub(E2, W2);
    v[3] = cadd(E3, W3);  v[7] = csub(E3, W3);
}

// Two-stage radix-8 64-pt FFT on a [64][KT] smem tile, along dim0, thread
// owns (kk = t&31, r0 = t>>5). Output digit-reversed: X[m] at row rev8x8(m).
__device__ __forceinline__ void fft64_tile(float2* tile, int kk, int r0) {
    {   // stage 1: butterflies over stride 8, twiddle W64^{i*k}
        int i = r0;
        float2 v[8];
        #pragma unroll
        for (int j = 0; j < 8; j++) v[j] = tile[(i + 8 * j) * KT + kk];
        dft8(v);
        #pragma unroll
        for (int k = 1; k < 8; k++) v[k] = cmul(v[k], __ldg(&g_W64[i * k]));
        #pragma unroll
        for (int j = 0; j < 8; j++) tile[(i + 8 * j) * KT + kk] = v[j];
    }
    __syncthreads();
    {   // stage 2: contiguous groups of 8
        float2 v[8];
        #pragma unroll
        for (int j = 0; j < 8; j++) v[j] = tile[(8 * r0 + j) * KT + kk];
        dft8(v);
        #pragma unroll
        for (int j = 0; j < 8; j++) tile[(8 * r0 + j) * KT + kk] = v[j];
    }
    __syncthreads();
}

// ---------------------------------------------------------------- init tables
__global__ void k_init() {
    int i = blockIdx.x * blockDim.x + threadIdx.x;
    if (i < 144) {
        int h1 = i / 12, r = i - h1 * 12;
        float s, c;
        sincospif(-2.0f * (float)(h1 * r) / 12.0f, &s, &c);
        g_w12[i] = make_float2(c, s);
    }
    if (i < 768) {
        float s, c;
        sincospif(-2.0f * (float)i / 768.0f, &s, &c);
        g_w768[i] = make_float2(c, s);
    }
    if (i < 64) {
        float s, c;
        sincospif(-(float)i / 32.0f, &s, &c);      // -2*pi*i/64
        g_W64[i] = make_float2(c, s);
    }
    if (i < 4096) {
        float s, c;
        sincospif(-(float)i / 2048.0f, &s, &c);    // -2*pi*i/4096
        g_W4096[i] = make_float2(c, s);
    }
}

// ------------------------------------------------- stage A: hidden-dim FFT(768)
// PAIR TRICK: rows (2f, 2f+1) packed as z = x_even + i*x_odd -> ONE complex
// 768-pt FFT per pair (we were computing the full spectrum and discarding half
// anyway). Unpack: Ya[k] = (Z[k]+conj(Z[768-k]))/2, Yb[k] = -i(Z[k]-conj(..))/2.
// Halves phase-1 LDS stream and 64-pt FFT count at equal FFMA cost. Exact math.
__global__ __launch_bounds__(256) void k_stageA(const float* __restrict__ x) {
    __shared__ float2 sz[2 * HID];              // 12 KB: packed row pairs
    __shared__ float2 sG[2 * 12 * 65];          // 12.2 KB, stride-65 padded
    __shared__ float2 sw768[768];               // 6 KB
    __shared__ float2 sw12[144];
    __shared__ float2 sw64[64];
    int rowBase = blockIdx.x * AROWS;
    int b    = rowBase >> 12;
    int srow = rowBase & 4095;
    const float* xp = x + (size_t)rowBase * HID;
    int t = threadIdx.x;
    for (int i = t; i < 2 * HID; i += 256) {
        int f = i / HID, j = i - f * HID;
        sz[i] = make_float2(xp[(2 * f) * HID + j], xp[(2 * f + 1) * HID + j]);
    }
    for (int i = t; i < 768; i += 256) sw768[i] = g_w768[i];
    if (t < 144) sw12[t] = g_w12[t];
    int tt = t - 192;
    if (tt >= 0 && tt < 64) sw64[tt] = g_W64[tt];
    __syncthreads();

    // phase 1: 12-pt DFTs (complex input) + fused W768 twiddle
    for (int e = t; e < 2 * HID; e += 256) {
        int f = e / HID, idx = e - f * HID;
        int h0 = idx / 12, k1 = idx - h0 * 12;
        float2 acc = make_float2(0.f, 0.f);
        #pragma unroll
        for (int h1 = 0; h1 < 12; h1++) {
            float2 z = sz[f * HID + h0 + 64 * h1];
            float2 w = sw12[h1 * 12 + k1];
            acc.x = fmaf(z.x, w.x, fmaf(-z.y, w.y, acc.x));
            acc.y = fmaf(z.x, w.y, fmaf( z.y, w.x, acc.y));
        }
        float2 tw = sw768[h0 * k1];             // h0*k1 <= 693
        sG[(f * 12 + k1) * 65 + h0] = cmul(acc, tw);
    }
    __syncthreads();

    // phase 2: 24 independent 64-pt FFTs (radix-8 DIF, 2 stages), 192 tasks
    if (t < 192) {
        int ff = t % 24, i = t / 24;
        float2* s = &sG[ff * 65];
        float2 v[8];
        #pragma unroll
        for (int j = 0; j < 8; j++) v[j] = s[i + 8 * j];
        dft8(v);
        #pragma unroll
        for (int k = 1; k < 8; k++) v[k] = cmul(v[k], sw64[i * k]);
        #pragma unroll
        for (int j = 0; j < 8; j++) s[i + 8 * j] = v[j];
    }
    __syncthreads();
    if (t < 192) {
        int ff = t % 24, blk = t / 24;
        float2* s = &sG[ff * 65 + 8 * blk];
        float2 v[8];
        #pragma unroll
        for (int j = 0; j < 8; j++) v[j] = s[j];
        dft8(v);
        #pragma unroll
        for (int j = 0; j < 8; j++) s[j] = v[j];
    }
    __syncthreads();

    // unpack pairs + write g_Y[b][s][k], k = k1 + 12*k2, slot p = rev(k2)
    for (int k = t; k < KH; k += 256) {
        int k2 = k / 12, k1 = k - k2 * 12;
        int p  = rev8x8(k2);
        int km = (768 - k) % 768;               // conjugate-mirror bin
        int kk2 = km / 12, kk1 = km - kk2 * 12;
        int pk = rev8x8(kk2);
        #pragma unroll
        for (int f = 0; f < 2; f++) {
            float2 Z  = sG[(f * 12 + k1)  * 65 + p];
            float2 Zk = sG[(f * 12 + kk1) * 65 + pk];
            float2 Ya = make_float2(0.5f * (Z.x + Zk.x), 0.5f * (Z.y - Zk.y));
            float2 Yb = make_float2(0.5f * (Z.y + Zk.y), 0.5f * (Zk.x - Z.x));
            g_Y[((size_t)(b * SEQ) + srow + 2 * f)     * KH + k] = Ya;
            g_Y[((size_t)(b * SEQ) + srow + 2 * f + 1) * KH + k] = Yb;
        }
    }
}

// --------------------------------------- B1: seq FFT step 1 (over s1) + twiddle
// (unchanged from R11 best)
__global__ __launch_bounds__(256) void k_B1() {
    __shared__ float2 tile[64 * KT];   // 16 KB
    int k0 = blockIdx.x * KT;
    int s0 = blockIdx.y;
    int b  = blockIdx.z;
    int t  = threadIdx.x;
    int kk = t & 31, r0 = t >> 5;
    int k  = k0 + kk;
    bool ok = (k < KH);

    #pragma unroll
    for (int j = 0; j < 8; j++) {
        int s1 = r0 + 8 * j;
        tile[s1 * KT + kk] = ok ?
            g_Y[((size_t)(b * SEQ) + s0 + 64 * s1) * KH + k] : make_float2(0.f, 0.f);
    }
    __syncthreads();

    fft64_tile(tile, kk, r0);

    #pragma unroll
    for (int m0b = 0; m0b < 64; m0b += 8) {
        int m0 = m0b + r0;
        float2 v = tile[rev8x8(m0) * KT + kk];
        float2 w = __ldg(&g_W4096[s0 * m0]);         // warp-uniform broadcast
        v = cmul(v, w);
        if (ok)
            g_Y2[(((size_t)b * 64 + m0) * 64 + s0) * KH + k] = v;
    }
}

// --------------------------------------- B2: seq FFT step 2, real part + mirror
// (unchanged from R11 best)
__global__ __launch_bounds__(256) void k_B2(float* __restrict__ out) {
    __shared__ float2 tile[64 * KT];   // 16 KB
    int k0 = blockIdx.x * KT;
    int m0 = blockIdx.y;
    int b  = blockIdx.z;
    int t  = threadIdx.x;
    int kk = t & 31, r0 = t >> 5;
    int k  = k0 + kk;
    bool ok = (k < KH);

    #pragma unroll
    for (int j = 0; j < 8; j++) {
        int s0 = r0 + 8 * j;
        tile[s0 * KT + kk] = ok ?
            g_Y2[(((size_t)b * 64 + m0) * 64 + s0) * KH + k] : make_float2(0.f, 0.f);
    }
    __syncthreads();

    fft64_tile(tile, kk, r0);

    bool domir = (k >= 1 && k <= 383);
    #pragma unroll
    for (int m1b = 0; m1b < 64; m1b += 8) {
        int m1 = m1b + r0;
        float zr = tile[rev8x8(m1) * KT + kk].x;
        int m = m0 + 64 * m1;
        if (ok)
            out[((size_t)b * SEQ + m) * HID + k] = zr;
        if (domir) {
            int mp = (SEQ - m) & 4095;
            out[((size_t)b * SEQ + mp) * HID + (HID - k)] = zr;
        }
    }
}

extern "C" void kernel_launch(void* const* d_in, const int* in_sizes, int n_in,
                              void* d_out, int out_size) {
    (void)in_sizes; (void)n_in; (void)out_size;
    const float* x = (const float*)d_in[0];
    float* out = (float*)d_out;

    k_init   <<<16, 256>>>();
    k_stageA <<<NB * SEQ / AROWS, 256>>>(x);        // 8192 blocks
    k_B1     <<<dim3(NKT, 64, NB), 256>>>();        // 6656 blocks
    k_B2     <<<dim3(NKT, 64, NB), 256>>>(out);     // 6656 blocks
}

// round 13
// speedup vs baseline: 6.2116x; 1.1871x over previous
#include <cuda_runtime.h>
#include <math_constants.h>

#define SEQ  4096
#define HID  768
#define NB   8
#define KH   385   // HID/2 + 1 (Hermitian half + Nyquist)
#define AROWS 8    // real rows per block -> 4 complex FFTs (pair trick)
#define KT   32    // k-tile width for B1/B2
#define NKT  13    // ceil(385/32)

// ---------------------------------------------------------------- device state
__device__ float2 g_Y [NB * SEQ * KH];        // A out:  [b][s][k]   (~101 MB)
__device__ float2 g_Y2[NB * 64 * 64 * KH];    // B1 out: [b][m0][s0][k] (~101 MB)
__device__ float2 g_w768t[12 * 64];           // W768^{h0*q}, TRANSPOSED [q][h0]
__device__ float2 g_W64[64];                  // e^{-2pi i p / 64}
__device__ float2 g_W4096[4096];              // e^{-2pi i p / 4096}

// ---------------------------------------------------------------- helpers
__device__ __forceinline__ float2 cadd(float2 a, float2 b){ return make_float2(a.x+b.x, a.y+b.y); }
__device__ __forceinline__ float2 csub(float2 a, float2 b){ return make_float2(a.x-b.x, a.y-b.y); }
__device__ __forceinline__ float2 mni (float2 a){ return make_float2(a.y, -a.x); }   // * (-i)
__device__ __forceinline__ float2 cmul(float2 a, float2 w){
    return make_float2(fmaf(a.x, w.x, -a.y * w.y), fmaf(a.x, w.y, a.y * w.x));
}
__device__ __forceinline__ int rev8x8(int m){ return ((m & 7) << 3) | (m >> 3); }

// 8-point DFT (negative exponent), in place. ~56 flops.
__device__ __forceinline__ void dft8(float2* v) {
    const float C = 0.70710678118654752f;
    float2 t0 = cadd(v[0], v[4]), t1 = csub(v[0], v[4]);
    float2 t2 = cadd(v[2], v[6]), t3 = csub(v[2], v[6]);
    float2 E0 = cadd(t0, t2), E2 = csub(t0, t2);
    float2 mt3 = mni(t3);
    float2 E1 = cadd(t1, mt3), E3 = csub(t1, mt3);
    float2 u0 = cadd(v[1], v[5]), u1 = csub(v[1], v[5]);
    float2 u2 = cadd(v[3], v[7]), u3 = csub(v[3], v[7]);
    float2 O0 = cadd(u0, u2), O2 = csub(u0, u2);
    float2 mu3 = mni(u3);
    float2 O1 = cadd(u1, mu3), O3 = csub(u1, mu3);
    float2 W1 = make_float2(C * (O1.x + O1.y), C * (O1.y - O1.x));   // W8^1 * O1
    float2 W2 = mni(O2);                                             // W8^2 * O2
    float2 W3 = make_float2(C * (O3.y - O3.x), -C * (O3.x + O3.y));  // W8^3 * O3
    v[0] = cadd(E0, O0);  v[4] = csub(E0, O0);
    v[1] = cadd(E1, W1);  v[5] = csub(E1, W1);
    v[2] = cadd(E2, W2);  v[6] = csub(E2, W2);
    v[3] = cadd(E3, W3);  v[7] = csub(E3, W3);
}

// Two-stage radix-8 64-pt FFT on a [64][KT] smem tile (unchanged, verified).
__device__ __forceinline__ void fft64_tile(float2* tile, int kk, int r0) {
    {
        int i = r0;
        float2 v[8];
        #pragma unroll
        for (int j = 0; j < 8; j++) v[j] = tile[(i + 8 * j) * KT + kk];
        dft8(v);
        #pragma unroll
        for (int k = 1; k < 8; k++) v[k] = cmul(v[k], __ldg(&g_W64[i * k]));
        #pragma unroll
        for (int j = 0; j < 8; j++) tile[(i + 8 * j) * KT + kk] = v[j];
    }
    __syncthreads();
    {
        float2 v[8];
        #pragma unroll
        for (int j = 0; j < 8; j++) v[j] = tile[(8 * r0 + j) * KT + kk];
        dft8(v);
        #pragma unroll
        for (int j = 0; j < 8; j++) tile[(8 * r0 + j) * KT + kk] = v[j];
    }
    __syncthreads();
}

// ---------------------------------------------------------------- init tables
__global__ void k_init() {
    int i = blockIdx.x * blockDim.x + threadIdx.x;
    if (i < 12 * 64) {
        int q = i / 64, h0 = i - q * 64;
        float s, c;
        sincospif(-(float)(h0 * q) / 384.0f, &s, &c);   // -2pi*h0*q/768
        g_w768t[i] = make_float2(c, s);
    }
    if (i < 64) {
        float s, c;
        sincospif(-(float)i / 32.0f, &s, &c);      // -2*pi*i/64
        g_W64[i] = make_float2(c, s);
    }
    if (i < 4096) {
        float s, c;
        sincospif(-(float)i / 2048.0f, &s, &c);    // -2*pi*i/4096
        g_W4096[i] = make_float2(c, s);
    }
}

// ------------------------------------------------- stage A: hidden-dim FFT(768)
// 8 real rows -> 4 packed complex rows (pair trick). Phase 1: ONE thread per
// (pair f, h0): registers-resident radix-4x3 FFT-12 over h1 (inputs loaded once),
// then W768^{h0 q} twiddle from transposed table (conflict-free LDS).
__global__ __launch_bounds__(256) void k_stageA(const float* __restrict__ x) {
    __shared__ float2 sG[4 * 12 * 65];          // 24.96 KB; also aliased as sz
    __shared__ float2 sw768t[12 * 64];          // 6 KB
    __shared__ float2 sw64[64];                 // 0.5 KB
    float2* sz = sG;                            // packed input, 4*768 <= 4*12*65

    int rowBase = blockIdx.x * AROWS;
    int b    = rowBase >> 12;
    int srow = rowBase & 4095;
    const float* xp = x + (size_t)rowBase * HID;
    int t = threadIdx.x;
    for (int i = t; i < 4 * HID; i += 256) {
        int f = i / HID, j = i - f * HID;
        sz[i] = make_float2(xp[(2 * f) * HID + j], xp[(2 * f + 1) * HID + j]);
    }
    for (int i = t; i < 12 * 64; i += 256) sw768t[i] = g_w768t[i];
    if (t < 64) sw64[t] = g_W64[t];
    __syncthreads();

    // ---- phase 1: per-thread FFT-12 ----
    {
        int f = t >> 6, h0 = t & 63;
        float2 z[12];
        #pragma unroll
        for (int h1 = 0; h1 < 12; h1++) z[h1] = sz[f * HID + h0 + 64 * h1];
        __syncthreads();                        // all sz reads done (sG aliases)

        // DFT4 over n1 (h1 = 3*n1 + n2) for each n2
        float2 A[3][4];
        #pragma unroll
        for (int n2 = 0; n2 < 3; n2++) {
            float2 a0 = cadd(z[n2],     z[6 + n2]);
            float2 a1 = csub(z[n2],     z[6 + n2]);
            float2 a2 = cadd(z[3 + n2], z[9 + n2]);
            float2 a3 = csub(z[3 + n2], z[9 + n2]);
            A[n2][0] = cadd(a0, a2);
            A[n2][1] = cadd(a1, mni(a3));
            A[n2][2] = csub(a0, a2);
            A[n2][3] = csub(a1, mni(a3));
        }
        // W12^{n2*k1'} twiddles (constants; ^3 = -i, ^6 = -1)
        const float H = 0.5f, S3 = 0.86602540378443865f;
        A[1][1] = cmul(A[1][1], make_float2( S3, -H ));   // W12^1
        A[1][2] = cmul(A[1][2], make_float2( H , -S3));   // W12^2
        A[1][3] = mni (A[1][3]);                          // W12^3
        A[2][1] = cmul(A[2][1], make_float2( H , -S3));   // W12^2
        A[2][2] = cmul(A[2][2], make_float2(-H , -S3));   // W12^4
        A[2][3] = make_float2(-A[2][3].x, -A[2][3].y);    // W12^6
        // DFT3 over n2 for each k1'; output q = k1' + 4*k2'
        float2 Xo[12];
        #pragma unroll
        for (int k1p = 0; k1p < 4; k1p++) {
            float2 b0 = A[0][k1p], b1 = A[1][k1p], b2 = A[2][k1p];
            float2 tt = cadd(b1, b2), dd = csub(b1, b2);
            float2 s  = make_float2(fmaf(-0.5f, tt.x, b0.x),
                                    fmaf(-0.5f, tt.y, b0.y));
            float2 md = mni(dd);
            float2 e  = make_float2(S3 * md.x, S3 * md.y);
            Xo[k1p]     = cadd(b0, tt);
            Xo[k1p + 4] = cadd(s, e);
            Xo[k1p + 8] = csub(s, e);
        }
        // W768^{h0*q} twiddle + store to sG[(f*12+q)*65 + h0]
        sG[(f * 12 + 0) * 65 + h0] = Xo[0];     // q=0: twiddle = 1
        #pragma unroll
        for (int q = 1; q < 12; q++) {
            float2 w = sw768t[q * 64 + h0];     // lane-consecutive: conflict-free
            sG[(f * 12 + q) * 65 + h0] = cmul(Xo[q], w);
        }
    }
    __syncthreads();

    // ---- phase 2: 48 independent 64-pt FFTs (radix-8 DIF, 2 stages) ----
    for (int task = t; task < 48 * 8; task += 256) {
        int ff = task % 48, i = task / 48;
        float2* s = &sG[ff * 65];
        float2 v[8];
        #pragma unroll
        for (int j = 0; j < 8; j++) v[j] = s[i + 8 * j];
        dft8(v);
        #pragma unroll
        for (int k = 1; k < 8; k++) v[k] = cmul(v[k], sw64[i * k]);
        #pragma unroll
        for (int j = 0; j < 8; j++) s[i + 8 * j] = v[j];
    }
    __syncthreads();
    for (int task = t; task < 48 * 8; task += 256) {
        int ff = task % 48, blk = task / 48;
        float2* s = &sG[ff * 65 + 8 * blk];
        float2 v[8];
        #pragma unroll
        for (int j = 0; j < 8; j++) v[j] = s[j];
        dft8(v);
        #pragma unroll
        for (int j = 0; j < 8; j++) s[j] = v[j];
    }
    __syncthreads();

    // ---- unpack pairs + write g_Y[b][s][k], k = k1 + 12*k2, slot p = rev(k2)
    for (int k = t; k < KH; k += 256) {
        int k2 = k / 12, k1 = k - k2 * 12;
        int p  = rev8x8(k2);
        int km = (768 - k) % 768;               // conjugate-mirror bin
        int kk2 = km / 12, kk1 = km - kk2 * 12;
        int pk = rev8x8(kk2);
        #pragma unroll
        for (int f = 0; f < 4; f++) {
            float2 Z  = sG[(f * 12 + k1)  * 65 + p];
            float2 Zk = sG[(f * 12 + kk1) * 65 + pk];
            float2 Ya = make_float2(0.5f * (Z.x + Zk.x), 0.5f * (Z.y - Zk.y));
            float2 Yb = make_float2(0.5f * (Z.y + Zk.y), 0.5f * (Zk.x - Z.x));
            g_Y[((size_t)(b * SEQ) + srow + 2 * f)     * KH + k] = Ya;
            g_Y[((size_t)(b * SEQ) + srow + 2 * f + 1) * KH + k] = Yb;
        }
    }
}

// --------------------------------------- B1: seq FFT step 1 (over s1) + twiddle
// (unchanged from R12 best)
__global__ __launch_bounds__(256) void k_B1() {
    __shared__ float2 tile[64 * KT];   // 16 KB
    int k0 = blockIdx.x * KT;
    int s0 = blockIdx.y;
    int b  = blockIdx.z;
    int t  = threadIdx.x;
    int kk = t & 31, r0 = t >> 5;
    int k  = k0 + kk;
    bool ok = (k < KH);

    #pragma unroll
    for (int j = 0; j < 8; j++) {
        int s1 = r0 + 8 * j;
        tile[s1 * KT + kk] = ok ?
            g_Y[((size_t)(b * SEQ) + s0 + 64 * s1) * KH + k] : make_float2(0.f, 0.f);
    }
    __syncthreads();

    fft64_tile(tile, kk, r0);

    #pragma unroll
    for (int m0b = 0; m0b < 64; m0b += 8) {
        int m0 = m0b + r0;
        float2 v = tile[rev8x8(m0) * KT + kk];
        float2 w = __ldg(&g_W4096[s0 * m0]);         // warp-uniform broadcast
        v = cmul(v, w);
        if (ok)
            g_Y2[(((size_t)b * 64 + m0) * 64 + s0) * KH + k] = v;
    }
}

// --------------------------------------- B2: seq FFT step 2, real part + mirror
// (unchanged from R12 best)
__global__ __launch_bounds__(256) void k_B2(float* __restrict__ out) {
    __shared__ float2 tile[64 * KT];   // 16 KB
    int k0 = blockIdx.x * KT;
    int m0 = blockIdx.y;
    int b  = blockIdx.z;
    int t  = threadIdx.x;
    int kk = t & 31, r0 = t >> 5;
    int k  = k0 + kk;
    bool ok = (k < KH);

    #pragma unroll
    for (int j = 0; j < 8; j++) {
        int s0 = r0 + 8 * j;
        tile[s0 * KT + kk] = ok ?
            g_Y2[(((size_t)b * 64 + m0) * 64 + s0) * KH + k] : make_float2(0.f, 0.f);
    }
    __syncthreads();

    fft64_tile(tile, kk, r0);

    bool domir = (k >= 1 && k <= 383);
    #pragma unroll
    for (int m1b = 0; m1b < 64; m1b += 8) {
        int m1 = m1b + r0;
        float zr = tile[rev8x8(m1) * KT + kk].x;
        int m = m0 + 64 * m1;
        if (ok)
            out[((size_t)b * SEQ + m) * HID + k] = zr;
        if (domir) {
            int mp = (SEQ - m) & 4095;
            out[((size_t)b * SEQ + mp) * HID + (HID - k)] = zr;
        }
    }
}

extern "C" void kernel_launch(void* const* d_in, const int* in_sizes, int n_in,
                              void* d_out, int out_size) {
    (void)in_sizes; (void)n_in; (void)out_size;
    const float* x = (const float*)d_in[0];
    float* out = (float*)d_out;

    k_init   <<<16, 256>>>();
    k_stageA <<<NB * SEQ / AROWS, 256>>>(x);        // 4096 blocks
    k_B1     <<<dim3(NKT, 64, NB), 256>>>();        // 6656 blocks
    k_B2     <<<dim3(NKT, 64, NB), 256>>>(out);     // 6656 blocks
}

// round 14
// speedup vs baseline: 7.0438x; 1.1340x over previous
#include <cuda_runtime.h>
#include <cuda_fp16.h>
#include <math_constants.h>

#define SEQ  4096
#define HID  768
#define NB   8
#define KH   385   // HID/2 + 1 (Hermitian half + Nyquist)
#define AROWS 8    // real rows per block -> 4 complex FFTs (pair trick)
#define KT   32    // k-tile width for B1/B2
#define NKT  13    // ceil(385/32)

// ---------------------------------------------------------------- device state
__device__ __half2 g_Yh [NB * SEQ * KH];       // A out:  [b][s][k]   (~50 MB, fp16)
__device__ __half2 g_Y2h[NB * 64 * 64 * KH];   // B1 out: [b][m0][s0][k] (~50 MB)
__device__ float2 g_w768t[12 * 64];            // W768^{h0*q}, TRANSPOSED [q][h0]
__device__ float2 g_W64[64];                   // e^{-2pi i p / 64}
__device__ float2 g_W4096[4096];               // e^{-2pi i p / 4096}

// ---------------------------------------------------------------- helpers
__device__ __forceinline__ float2 cadd(float2 a, float2 b){ return make_float2(a.x+b.x, a.y+b.y); }
__device__ __forceinline__ float2 csub(float2 a, float2 b){ return make_float2(a.x-b.x, a.y-b.y); }
__device__ __forceinline__ float2 mni (float2 a){ return make_float2(a.y, -a.x); }   // * (-i)
__device__ __forceinline__ float2 cmul(float2 a, float2 w){
    return make_float2(fmaf(a.x, w.x, -a.y * w.y), fmaf(a.x, w.y, a.y * w.x));
}
__device__ __forceinline__ int rev8x8(int m){ return ((m & 7) << 3) | (m >> 3); }
__device__ __forceinline__ __half2 f2h(float2 v){ return __floats2half2_rn(v.x, v.y); }
__device__ __forceinline__ float2 h2f(__half2 h){ return __half22float2(h); }

// 8-point DFT (negative exponent), in place. ~56 flops.
__device__ __forceinline__ void dft8(float2* v) {
    const float C = 0.70710678118654752f;
    float2 t0 = cadd(v[0], v[4]), t1 = csub(v[0], v[4]);
    float2 t2 = cadd(v[2], v[6]), t3 = csub(v[2], v[6]);
    float2 E0 = cadd(t0, t2), E2 = csub(t0, t2);
    float2 mt3 = mni(t3);
    float2 E1 = cadd(t1, mt3), E3 = csub(t1, mt3);
    float2 u0 = cadd(v[1], v[5]), u1 = csub(v[1], v[5]);
    float2 u2 = cadd(v[3], v[7]), u3 = csub(v[3], v[7]);
    float2 O0 = cadd(u0, u2), O2 = csub(u0, u2);
    float2 mu3 = mni(u3);
    float2 O1 = cadd(u1, mu3), O3 = csub(u1, mu3);
    float2 W1 = make_float2(C * (O1.x + O1.y), C * (O1.y - O1.x));   // W8^1 * O1
    float2 W2 = mni(O2);                                             // W8^2 * O2
    float2 W3 = make_float2(C * (O3.y - O3.x), -C * (O3.x + O3.y));  // W8^3 * O3
    v[0] = cadd(E0, O0);  v[4] = csub(E0, O0);
    v[1] = cadd(E1, W1);  v[5] = csub(E1, W1);
    v[2] = cadd(E2, W2);  v[6] = csub(E2, W2);
    v[3] = cadd(E3, W3);  v[7] = csub(E3, W3);
}

// Two-stage radix-8 64-pt FFT on a [64][KT] smem tile (unchanged, verified).
__device__ __forceinline__ void fft64_tile(float2* tile, int kk, int r0) {
    {
        int i = r0;
        float2 v[8];
        #pragma unroll
        for (int j = 0; j < 8; j++) v[j] = tile[(i + 8 * j) * KT + kk];
        dft8(v);
        #pragma unroll
        for (int k = 1; k < 8; k++) v[k] = cmul(v[k], __ldg(&g_W64[i * k]));
        #pragma unroll
        for (int j = 0; j < 8; j++) tile[(i + 8 * j) * KT + kk] = v[j];
    }
    __syncthreads();
    {
        float2 v[8];
        #pragma unroll
        for (int j = 0; j < 8; j++) v[j] = tile[(8 * r0 + j) * KT + kk];
        dft8(v);
        #pragma unroll
        for (int j = 0; j < 8; j++) tile[(8 * r0 + j) * KT + kk] = v[j];
    }
    __syncthreads();
}

// ---------------------------------------------------------------- init tables
__global__ void k_init() {
    int i = blockIdx.x * blockDim.x + threadIdx.x;
    if (i < 12 * 64) {
        int q = i / 64, h0 = i - q * 64;
        float s, c;
        sincospif(-(float)(h0 * q) / 384.0f, &s, &c);   // -2pi*h0*q/768
        g_w768t[i] = make_float2(c, s);
    }
    if (i < 64) {
        float s, c;
        sincospif(-(float)i / 32.0f, &s, &c);      // -2*pi*i/64
        g_W64[i] = make_float2(c, s);
    }
    if (i < 4096) {
        float s, c;
        sincospif(-(float)i / 2048.0f, &s, &c);    // -2*pi*i/4096
        g_W4096[i] = make_float2(c, s);
    }
}

// ------------------------------------------------- stage A: hidden-dim FFT(768)
// 8 real rows -> 4 packed complex rows (pair trick). Phase 1: per-thread
// register FFT-12 (radix 4x3). fp16 output at the global boundary only.
__global__ __launch_bounds__(256) void k_stageA(const float* __restrict__ x) {
    __shared__ float2 sG[4 * 12 * 65];          // 24.96 KB; also aliased as sz
    __shared__ float2 sw768t[12 * 64];          // 6 KB
    __shared__ float2 sw64[64];                 // 0.5 KB
    float2* sz = sG;                            // packed input, 4*768 <= 4*12*65

    int rowBase = blockIdx.x * AROWS;
    int b    = rowBase >> 12;
    int srow = rowBase & 4095;
    const float* xp = x + (size_t)rowBase * HID;
    int t = threadIdx.x;
    for (int i = t; i < 4 * HID; i += 256) {
        int f = i / HID, j = i - f * HID;
        sz[i] = make_float2(xp[(2 * f) * HID + j], xp[(2 * f + 1) * HID + j]);
    }
    for (int i = t; i < 12 * 64; i += 256) sw768t[i] = g_w768t[i];
    if (t < 64) sw64[t] = g_W64[t];
    __syncthreads();

    // ---- phase 1: per-thread FFT-12 ----
    {
        int f = t >> 6, h0 = t & 63;
        float2 z[12];
        #pragma unroll
        for (int h1 = 0; h1 < 12; h1++) z[h1] = sz[f * HID + h0 + 64 * h1];
        __syncthreads();                        // all sz reads done (sG aliases)

        float2 A[3][4];
        #pragma unroll
        for (int n2 = 0; n2 < 3; n2++) {
            float2 a0 = cadd(z[n2],     z[6 + n2]);
            float2 a1 = csub(z[n2],     z[6 + n2]);
            float2 a2 = cadd(z[3 + n2], z[9 + n2]);
            float2 a3 = csub(z[3 + n2], z[9 + n2]);
            A[n2][0] = cadd(a0, a2);
            A[n2][1] = cadd(a1, mni(a3));
            A[n2][2] = csub(a0, a2);
            A[n2][3] = csub(a1, mni(a3));
        }
        const float H = 0.5f, S3 = 0.86602540378443865f;
        A[1][1] = cmul(A[1][1], make_float2( S3, -H ));   // W12^1
        A[1][2] = cmul(A[1][2], make_float2( H , -S3));   // W12^2
        A[1][3] = mni (A[1][3]);                          // W12^3
        A[2][1] = cmul(A[2][1], make_float2( H , -S3));   // W12^2
        A[2][2] = cmul(A[2][2], make_float2(-H , -S3));   // W12^4
        A[2][3] = make_float2(-A[2][3].x, -A[2][3].y);    // W12^6
        float2 Xo[12];
        #pragma unroll
        for (int k1p = 0; k1p < 4; k1p++) {
            float2 b0 = A[0][k1p], b1 = A[1][k1p], b2 = A[2][k1p];
            float2 tt = cadd(b1, b2), dd = csub(b1, b2);
            float2 s  = make_float2(fmaf(-0.5f, tt.x, b0.x),
                                    fmaf(-0.5f, tt.y, b0.y));
            float2 md = mni(dd);
            float2 e  = make_float2(S3 * md.x, S3 * md.y);
            Xo[k1p]     = cadd(b0, tt);
            Xo[k1p + 4] = cadd(s, e);
            Xo[k1p + 8] = csub(s, e);
        }
        sG[(f * 12 + 0) * 65 + h0] = Xo[0];     // q=0: twiddle = 1
        #pragma unroll
        for (int q = 1; q < 12; q++) {
            float2 w = sw768t[q * 64 + h0];     // lane-consecutive: conflict-free
            sG[(f * 12 + q) * 65 + h0] = cmul(Xo[q], w);
        }
    }
    __syncthreads();

    // ---- phase 2: 48 independent 64-pt FFTs (radix-8 DIF, 2 stages) ----
    for (int task = t; task < 48 * 8; task += 256) {
        int ff = task % 48, i = task / 48;
        float2* s = &sG[ff * 65];
        float2 v[8];
        #pragma unroll
        for (int j = 0; j < 8; j++) v[j] = s[i + 8 * j];
        dft8(v);
        #pragma unroll
        for (int k = 1; k < 8; k++) v[k] = cmul(v[k], sw64[i * k]);
        #pragma unroll
        for (int j = 0; j < 8; j++) s[i + 8 * j] = v[j];
    }
    __syncthreads();
    for (int task = t; task < 48 * 8; task += 256) {
        int ff = task % 48, blk = task / 48;
        float2* s = &sG[ff * 65 + 8 * blk];
        float2 v[8];
        #pragma unroll
        for (int j = 0; j < 8; j++) v[j] = s[j];
        dft8(v);
        #pragma unroll
        for (int j = 0; j < 8; j++) s[j] = v[j];
    }
    __syncthreads();

    // ---- unpack pairs + write g_Yh[b][s][k] (fp16), slot p = rev(k2)
    for (int k = t; k < KH; k += 256) {
        int k2 = k / 12, k1 = k - k2 * 12;
        int p  = rev8x8(k2);
        int km = (768 - k) % 768;               // conjugate-mirror bin
        int kk2 = km / 12, kk1 = km - kk2 * 12;
        int pk = rev8x8(kk2);
        #pragma unroll
        for (int f = 0; f < 4; f++) {
            float2 Z  = sG[(f * 12 + k1)  * 65 + p];
            float2 Zk = sG[(f * 12 + kk1) * 65 + pk];
            float2 Ya = make_float2(0.5f * (Z.x + Zk.x), 0.5f * (Z.y - Zk.y));
            float2 Yb = make_float2(0.5f * (Z.y + Zk.y), 0.5f * (Zk.x - Z.x));
            g_Yh[((size_t)(b * SEQ) + srow + 2 * f)     * KH + k] = f2h(Ya);
            g_Yh[((size_t)(b * SEQ) + srow + 2 * f + 1) * KH + k] = f2h(Yb);
        }
    }
}

// --------------------------------------- B1: seq FFT step 1 (over s1) + twiddle
__global__ __launch_bounds__(256) void k_B1() {
    __shared__ float2 tile[64 * KT];   // 16 KB
    int k0 = blockIdx.x * KT;
    int s0 = blockIdx.y;
    int b  = blockIdx.z;
    int t  = threadIdx.x;
    int kk = t & 31, r0 = t >> 5;
    int k  = k0 + kk;
    bool ok = (k < KH);

    #pragma unroll
    for (int j = 0; j < 8; j++) {
        int s1 = r0 + 8 * j;
        tile[s1 * KT + kk] = ok ?
            h2f(g_Yh[((size_t)(b * SEQ) + s0 + 64 * s1) * KH + k]) : make_float2(0.f, 0.f);
    }
    __syncthreads();

    fft64_tile(tile, kk, r0);

    #pragma unroll
    for (int m0b = 0; m0b < 64; m0b += 8) {
        int m0 = m0b + r0;
        float2 v = tile[rev8x8(m0) * KT + kk];
        float2 w = __ldg(&g_W4096[s0 * m0]);         // warp-uniform broadcast
        v = cmul(v, w);
        if (ok)
            g_Y2h[(((size_t)b * 64 + m0) * 64 + s0) * KH + k] = f2h(v);
    }
}

// --------------------------------------- B2: seq FFT step 2, real part + mirror
__global__ __launch_bounds__(256) void k_B2(float* __restrict__ out) {
    __shared__ float2 tile[64 * KT];   // 16 KB
    int k0 = blockIdx.x * KT;
    int m0 = blockIdx.y;
    int b  = blockIdx.z;
    int t  = threadIdx.x;
    int kk = t & 31, r0 = t >> 5;
    int k  = k0 + kk;
    bool ok = (k < KH);

    #pragma unroll
    for (int j = 0; j < 8; j++) {
        int s0 = r0 + 8 * j;
        tile[s0 * KT + kk] = ok ?
            h2f(g_Y2h[(((size_t)b * 64 + m0) * 64 + s0) * KH + k]) : make_float2(0.f, 0.f);
    }
    __syncthreads();

    fft64_tile(tile, kk, r0);

    bool domir = (k >= 1 && k <= 383);
    #pragma unroll
    for (int m1b = 0; m1b < 64; m1b += 8) {
        int m1 = m1b + r0;
        float zr = tile[rev8x8(m1) * KT + kk].x;
        int m = m0 + 64 * m1;
        if (ok)
            out[((size_t)b * SEQ + m) * HID + k] = zr;
        if (domir) {
            int mp = (SEQ - m) & 4095;
            out[((size_t)b * SEQ + mp) * HID + (HID - k)] = zr;
        }
    }
}

extern "C" void kernel_launch(void* const* d_in, const int* in_sizes, int n_in,
                              void* d_out, int out_size) {
    (void)in_sizes; (void)n_in; (void)out_size;
    const float* x = (const float*)d_in[0];
    float* out = (float*)d_out;

    k_init   <<<16, 256>>>();
    k_stageA <<<NB * SEQ / AROWS, 256>>>(x);        // 4096 blocks
    k_B1     <<<dim3(NKT, 64, NB), 256>>>();        // 6656 blocks
    k_B2     <<<dim3(NKT, 64, NB), 256>>>(out);     // 6656 blocks
}

// round 15
// speedup vs baseline: 8.0330x; 1.1404x over previous
#include <cuda_runtime.h>
#include <cuda_fp16.h>
#include <math_constants.h>

#define SEQ  4096
#define HID  768
#define NB   8
#define KH   385   // HID/2 + 1 (Hermitian half + Nyquist)
#define AROWS 8    // real rows per block -> 4 complex FFTs (pair trick)
#define KT   32    // k-tile width for B1/B2
#define NKT  13    // ceil(385/32)

// ---------------------------------------------------------------- device state
__device__ __half2 g_Yh [NB * SEQ * KH];       // A out:  [b][s][k]   (~50 MB, fp16)
__device__ __half2 g_Y2h[NB * 64 * 64 * KH];   // B1 out: [b][m0][s0][k] (~50 MB)

// ---------------------------------------------------------------- helpers
__device__ __forceinline__ float2 cadd(float2 a, float2 b){ return make_float2(a.x+b.x, a.y+b.y); }
__device__ __forceinline__ float2 csub(float2 a, float2 b){ return make_float2(a.x-b.x, a.y-b.y); }
__device__ __forceinline__ float2 mni (float2 a){ return make_float2(a.y, -a.x); }   // * (-i)
__device__ __forceinline__ float2 cmul(float2 a, float2 w){
    return make_float2(fmaf(a.x, w.x, -a.y * w.y), fmaf(a.x, w.y, a.y * w.x));
}
__device__ __forceinline__ int rev8x8(int m){ return ((m & 7) << 3) | (m >> 3); }
__device__ __forceinline__ __half2 f2h(float2 v){ return __floats2half2_rn(v.x, v.y); }
__device__ __forceinline__ float2 h2f(__half2 h){ return __half22float2(h); }
// e^{-i*pi*x}
__device__ __forceinline__ float2 wexp(float x){
    float s, c; sincospif(-x, &s, &c); return make_float2(c, s);
}

// 8-point DFT (negative exponent), in place. ~56 flops.
__device__ __forceinline__ void dft8(float2* v) {
    const float C = 0.70710678118654752f;
    float2 t0 = cadd(v[0], v[4]), t1 = csub(v[0], v[4]);
    float2 t2 = cadd(v[2], v[6]), t3 = csub(v[2], v[6]);
    float2 E0 = cadd(t0, t2), E2 = csub(t0, t2);
    float2 mt3 = mni(t3);
    float2 E1 = cadd(t1, mt3), E3 = csub(t1, mt3);
    float2 u0 = cadd(v[1], v[5]), u1 = csub(v[1], v[5]);
    float2 u2 = cadd(v[3], v[7]), u3 = csub(v[3], v[7]);
    float2 O0 = cadd(u0, u2), O2 = csub(u0, u2);
    float2 mu3 = mni(u3);
    float2 O1 = cadd(u1, mu3), O3 = csub(u1, mu3);
    float2 W1 = make_float2(C * (O1.x + O1.y), C * (O1.y - O1.x));   // W8^1 * O1
    float2 W2 = mni(O2);                                             // W8^2 * O2
    float2 W3 = make_float2(C * (O3.y - O3.x), -C * (O3.x + O3.y));  // W8^3 * O3
    v[0] = cadd(E0, O0);  v[4] = csub(E0, O0);
    v[1] = cadd(E1, W1);  v[5] = csub(E1, W1);
    v[2] = cadd(E2, W2);  v[6] = csub(E2, W2);
    v[3] = cadd(E3, W3);  v[7] = csub(E3, W3);
}

// Apply W64^{i*k} to v[1..7] via power recurrence from w1 = W64^{i}.
__device__ __forceinline__ void tw64(float2* v, int i) {
    float2 w1 = wexp((float)i / 32.0f);
    float2 w = w1;
    v[1] = cmul(v[1], w);
    #pragma unroll
    for (int k = 2; k < 8; k++) { w = cmul(w, w1); v[k] = cmul(v[k], w); }
}

// ------------------------------------------------- stage A: hidden-dim FFT(768)
// 8 real rows -> 4 packed complex rows (pair trick). Phase 1: per-thread
// register FFT-12 (radix 4x3), twiddles by sincospif+recurrence (no tables).
__global__ __launch_bounds__(256) void k_stageA(const float* __restrict__ x) {
    __shared__ float2 sG[4 * 12 * 65];          // 24.96 KB; also aliased as sz
    float2* sz = sG;                            // packed input, 4*768 <= 4*12*65

    int rowBase = blockIdx.x * AROWS;
    int b    = rowBase >> 12;
    int srow = rowBase & 4095;
    const float* xp = x + (size_t)rowBase * HID;
    int t = threadIdx.x;
    for (int i = t; i < 4 * HID; i += 256) {
        int f = i / HID, j = i - f * HID;
        sz[i] = make_float2(xp[(2 * f) * HID + j], xp[(2 * f + 1) * HID + j]);
    }
    __syncthreads();

    // ---- phase 1: per-thread FFT-12 ----
    {
        int f = t >> 6, h0 = t & 63;
        float2 z[12];
        #pragma unroll
        for (int h1 = 0; h1 < 12; h1++) z[h1] = sz[f * HID + h0 + 64 * h1];
        __syncthreads();                        // all sz reads done (sG aliases)

        float2 A[3][4];
        #pragma unroll
        for (int n2 = 0; n2 < 3; n2++) {
            float2 a0 = cadd(z[n2],     z[6 + n2]);
            float2 a1 = csub(z[n2],     z[6 + n2]);
            float2 a2 = cadd(z[3 + n2], z[9 + n2]);
            float2 a3 = csub(z[3 + n2], z[9 + n2]);
            A[n2][0] = cadd(a0, a2);
            A[n2][1] = cadd(a1, mni(a3));
            A[n2][2] = csub(a0, a2);
            A[n2][3] = csub(a1, mni(a3));
        }
        const float H = 0.5f, S3 = 0.86602540378443865f;
        A[1][1] = cmul(A[1][1], make_float2( S3, -H ));   // W12^1
        A[1][2] = cmul(A[1][2], make_float2( H , -S3));   // W12^2
        A[1][3] = mni (A[1][3]);                          // W12^3
        A[2][1] = cmul(A[2][1], make_float2( H , -S3));   // W12^2
        A[2][2] = cmul(A[2][2], make_float2(-H , -S3));   // W12^4
        A[2][3] = make_float2(-A[2][3].x, -A[2][3].y);    // W12^6
        float2 Xo[12];
        #pragma unroll
        for (int k1p = 0; k1p < 4; k1p++) {
            float2 b0 = A[0][k1p], b1 = A[1][k1p], b2 = A[2][k1p];
            float2 tt = cadd(b1, b2), dd = csub(b1, b2);
            float2 s  = make_float2(fmaf(-0.5f, tt.x, b0.x),
                                    fmaf(-0.5f, tt.y, b0.y));
            float2 md = mni(dd);
            float2 e  = make_float2(S3 * md.x, S3 * md.y);
            Xo[k1p]     = cadd(b0, tt);
            Xo[k1p + 4] = cadd(s, e);
            Xo[k1p + 8] = csub(s, e);
        }
        // W768^{h0*q} twiddle via recurrence from w1 = W768^{h0}
        sG[(f * 12 + 0) * 65 + h0] = Xo[0];
        float2 w1 = wexp((float)h0 / 384.0f);
        float2 w = w1;
        sG[(f * 12 + 1) * 65 + h0] = cmul(Xo[1], w);
        #pragma unroll
        for (int q = 2; q < 12; q++) {
            w = cmul(w, w1);
            sG[(f * 12 + q) * 65 + h0] = cmul(Xo[q], w);
        }
    }
    __syncthreads();

    // ---- phase 2: 48 independent 64-pt FFTs (radix-8 DIF, 2 stages) ----
    for (int task = t; task < 48 * 8; task += 256) {
        int ff = task % 48, i = task / 48;
        float2* s = &sG[ff * 65];
        float2 v[8];
        #pragma unroll
        for (int j = 0; j < 8; j++) v[j] = s[i + 8 * j];
        dft8(v);
        tw64(v, i);
        #pragma unroll
        for (int j = 0; j < 8; j++) s[i + 8 * j] = v[j];
    }
    __syncthreads();
    for (int task = t; task < 48 * 8; task += 256) {
        int ff = task % 48, blk = task / 48;
        float2* s = &sG[ff * 65 + 8 * blk];
        float2 v[8];
        #pragma unroll
        for (int j = 0; j < 8; j++) v[j] = s[j];
        dft8(v);
        #pragma unroll
        for (int j = 0; j < 8; j++) s[j] = v[j];
    }
    __syncthreads();

    // ---- unpack pairs + write g_Yh[b][s][k] (fp16), slot p = rev(k2)
    for (int k = t; k < KH; k += 256) {
        int k2 = k / 12, k1 = k - k2 * 12;
        int p  = rev8x8(k2);
        int km = (768 - k) % 768;               // conjugate-mirror bin
        int kk2 = km / 12, kk1 = km - kk2 * 12;
        int pk = rev8x8(kk2);
        #pragma unroll
        for (int f = 0; f < 4; f++) {
            float2 Z  = sG[(f * 12 + k1)  * 65 + p];
            float2 Zk = sG[(f * 12 + kk1) * 65 + pk];
            float2 Ya = make_float2(0.5f * (Z.x + Zk.x), 0.5f * (Z.y - Zk.y));
            float2 Yb = make_float2(0.5f * (Z.y + Zk.y), 0.5f * (Zk.x - Z.x));
            g_Yh[((size_t)(b * SEQ) + srow + 2 * f)     * KH + k] = f2h(Ya);
            g_Yh[((size_t)(b * SEQ) + srow + 2 * f + 1) * KH + k] = f2h(Yb);
        }
    }
}

// --------------------------------------- B1: seq FFT step 1 (over s1) + twiddle
// Registers-first: stage1 straight from global (thread owns the stride-8 set),
// ONE smem exchange + barrier, stage2 + twiddle + store from registers.
__global__ __launch_bounds__(256) void k_B1() {
    __shared__ float2 tile[64 * KT];   // 16 KB
    int k0 = blockIdx.x * KT;
    int s0 = blockIdx.y;
    int b  = blockIdx.z;
    int t  = threadIdx.x;
    int kk = t & 31, r0 = t >> 5;
    int k  = k0 + kk;
    bool ok = (k < KH);

    // stage 1: rows s1 = r0 + 8j, loaded directly to registers
    float2 v[8];
    #pragma unroll
    for (int j = 0; j < 8; j++)
        v[j] = ok ? h2f(g_Yh[((size_t)(b * SEQ) + s0 + 64 * (r0 + 8 * j)) * KH + k])
                  : make_float2(0.f, 0.f);
    dft8(v);
    tw64(v, r0);                       // W64^{r0*k}
    #pragma unroll
    for (int j = 0; j < 8; j++) tile[(r0 + 8 * j) * KT + kk] = v[j];
    __syncthreads();

    // stage 2: contiguous group 8*r0..8*r0+7; output m0 = 8j + r0 (digit-reversed)
    float2 u[8];
    #pragma unroll
    for (int j = 0; j < 8; j++) u[j] = tile[(8 * r0 + j) * KT + kk];
    dft8(u);

    // twiddle W4096^{s0*m0}: base = W4096^{s0*r0}, step = W4096^{8*s0}
    float2 w    = wexp((float)(s0 * r0) / 2048.0f);
    float2 step = wexp((float)(8 * s0) / 2048.0f);
    #pragma unroll
    for (int j = 0; j < 8; j++) {
        int m0 = 8 * j + r0;
        if (ok)
            g_Y2h[(((size_t)b * 64 + m0) * 64 + s0) * KH + k] = f2h(cmul(u[j], w));
        w = cmul(w, step);
    }
}

// --------------------------------------- B2: seq FFT step 2, real part + mirror
__global__ __launch_bounds__(256) void k_B2(float* __restrict__ out) {
    __shared__ float2 tile[64 * KT];   // 16 KB
    int k0 = blockIdx.x * KT;
    int m0 = blockIdx.y;
    int b  = blockIdx.z;
    int t  = threadIdx.x;
    int kk = t & 31, r0 = t >> 5;
    int k  = k0 + kk;
    bool ok = (k < KH);

    // stage 1: rows s0 = r0 + 8j straight from global
    float2 v[8];
    #pragma unroll
    for (int j = 0; j < 8; j++)
        v[j] = ok ? h2f(g_Y2h[(((size_t)b * 64 + m0) * 64 + (r0 + 8 * j)) * KH + k])
                  : make_float2(0.f, 0.f);
    dft8(v);
    tw64(v, r0);
    #pragma unroll
    for (int j = 0; j < 8; j++) tile[(r0 + 8 * j) * KT + kk] = v[j];
    __syncthreads();

    // stage 2: contiguous group; thread holds m1 = 8j + r0
    float2 u[8];
    #pragma unroll
    for (int j = 0; j < 8; j++) u[j] = tile[(8 * r0 + j) * KT + kk];
    dft8(u);

    bool domir = (k >= 1 && k <= 383);
    #pragma unroll
    for (int j = 0; j < 8; j++) {
        int m1 = 8 * j + r0;
        float zr = u[j].x;
        int m = m0 + 64 * m1;
        if (ok)
            out[((size_t)b * SEQ + m) * HID + k] = zr;
        if (domir) {
            int mp = (SEQ - m) & 4095;
            out[((size_t)b * SEQ + mp) * HID + (HID - k)] = zr;
        }
    }
}

extern "C" void kernel_launch(void* const* d_in, const int* in_sizes, int n_in,
                              void* d_out, int out_size) {
    (void)in_sizes; (void)n_in; (void)out_size;
    const float* x = (const float*)d_in[0];
    float* out = (float*)d_out;

    k_stageA <<<NB * SEQ / AROWS, 256>>>(x);        // 4096 blocks
    k_B1     <<<dim3(NKT, 64, NB), 256>>>();        // 6656 blocks
    k_B2     <<<dim3(NKT, 64, NB), 256>>>(out);     // 6656 blocks
}

// round 16
// speedup vs baseline: 10.5039x; 1.3076x over previous
#include <cuda_runtime.h>
#include <cuda_fp16.h>
#include <math_constants.h>

#define SEQ  4096
#define HID  768
#define NB   8
#define KH   385   // HID/2 + 1 (Hermitian half + Nyquist)
#define AROWS 8    // real rows per block -> 4 complex FFTs (pair trick)
#define KT   32    // k-tile width for B1/B2
#define NKT  13    // ceil(385/32)

// ---------------------------------------------------------------- device state
__device__ __half2 g_Yh [NB * SEQ * KH];       // A out:  [b][s][k]   (~50 MB, fp16)
__device__ __half2 g_Y2h[NB * 64 * 64 * KH];   // B1 out: [b][m0][s0][k] (~50 MB)

// ---------------------------------------------------------------- helpers
__device__ __forceinline__ float2 cadd(float2 a, float2 b){ return make_float2(a.x+b.x, a.y+b.y); }
__device__ __forceinline__ float2 csub(float2 a, float2 b){ return make_float2(a.x-b.x, a.y-b.y); }
__device__ __forceinline__ float2 mni (float2 a){ return make_float2(a.y, -a.x); }   // * (-i)
__device__ __forceinline__ float2 cmul(float2 a, float2 w){
    return make_float2(fmaf(a.x, w.x, -a.y * w.y), fmaf(a.x, w.y, a.y * w.x));
}
__device__ __forceinline__ int rev8x8(int m){ return ((m & 7) << 3) | (m >> 3); }
__device__ __forceinline__ __half2 f2h(float2 v){ return __floats2half2_rn(v.x, v.y); }
__device__ __forceinline__ float2 h2f(__half2 h){ return __half22float2(h); }
// e^{-i*pi*x}
__device__ __forceinline__ float2 wexp(float x){
    float s, c; sincospif(-x, &s, &c); return make_float2(c, s);
}

// 8-point DFT (negative exponent), in place. ~56 flops.
__device__ __forceinline__ void dft8(float2* v) {
    const float C = 0.70710678118654752f;
    float2 t0 = cadd(v[0], v[4]), t1 = csub(v[0], v[4]);
    float2 t2 = cadd(v[2], v[6]), t3 = csub(v[2], v[6]);
    float2 E0 = cadd(t0, t2), E2 = csub(t0, t2);
    float2 mt3 = mni(t3);
    float2 E1 = cadd(t1, mt3), E3 = csub(t1, mt3);
    float2 u0 = cadd(v[1], v[5]), u1 = csub(v[1], v[5]);
    float2 u2 = cadd(v[3], v[7]), u3 = csub(v[3], v[7]);
    float2 O0 = cadd(u0, u2), O2 = csub(u0, u2);
    float2 mu3 = mni(u3);
    float2 O1 = cadd(u1, mu3), O3 = csub(u1, mu3);
    float2 W1 = make_float2(C * (O1.x + O1.y), C * (O1.y - O1.x));   // W8^1 * O1
    float2 W2 = mni(O2);                                             // W8^2 * O2
    float2 W3 = make_float2(C * (O3.y - O3.x), -C * (O3.x + O3.y));  // W8^3 * O3
    v[0] = cadd(E0, O0);  v[4] = csub(E0, O0);
    v[1] = cadd(E1, W1);  v[5] = csub(E1, W1);
    v[2] = cadd(E2, W2);  v[6] = csub(E2, W2);
    v[3] = cadd(E3, W3);  v[7] = csub(E3, W3);
}

// Apply W64^{i*k} to v[1..7] via power recurrence from w1 = W64^{i}.
__device__ __forceinline__ void tw64(float2* v, int i) {
    float2 w1 = wexp((float)i / 32.0f);
    float2 w = w1;
    v[1] = cmul(v[1], w);
    #pragma unroll
    for (int k = 2; k < 8; k++) { w = cmul(w, w1); v[k] = cmul(v[k], w); }
}

// ------------------------------------------------- stage A: hidden-dim FFT(768)
// 8 real rows -> 4 packed complex rows (pair trick). Phase 1 loads x STRAIGHT
// from global into registers (lane-coalesced; each element read once): no smem
// staging, no aliasing, 3 barriers instead of 5, MLP ~24 on the input reads.
__global__ __launch_bounds__(256) void k_stageA(const float* __restrict__ x) {
    __shared__ float2 sG[4 * 12 * 65];          // 24.96 KB

    int rowBase = blockIdx.x * AROWS;
    int b    = rowBase >> 12;
    int srow = rowBase & 4095;
    int t = threadIdx.x;

    // ---- phase 1: per-thread FFT-12, inputs direct from global ----
    {
        int f = t >> 6, h0 = t & 63;
        const float* xr0 = x + ((size_t)rowBase + 2 * f) * HID + h0;
        const float* xr1 = xr0 + HID;
        float2 z[12];
        #pragma unroll
        for (int h1 = 0; h1 < 12; h1++)
            z[h1] = make_float2(__ldg(xr0 + 64 * h1), __ldg(xr1 + 64 * h1));

        float2 A[3][4];
        #pragma unroll
        for (int n2 = 0; n2 < 3; n2++) {
            float2 a0 = cadd(z[n2],     z[6 + n2]);
            float2 a1 = csub(z[n2],     z[6 + n2]);
            float2 a2 = cadd(z[3 + n2], z[9 + n2]);
            float2 a3 = csub(z[3 + n2], z[9 + n2]);
            A[n2][0] = cadd(a0, a2);
            A[n2][1] = cadd(a1, mni(a3));
            A[n2][2] = csub(a0, a2);
            A[n2][3] = csub(a1, mni(a3));
        }
        const float H = 0.5f, S3 = 0.86602540378443865f;
        A[1][1] = cmul(A[1][1], make_float2( S3, -H ));   // W12^1
        A[1][2] = cmul(A[1][2], make_float2( H , -S3));   // W12^2
        A[1][3] = mni (A[1][3]);                          // W12^3
        A[2][1] = cmul(A[2][1], make_float2( H , -S3));   // W12^2
        A[2][2] = cmul(A[2][2], make_float2(-H , -S3));   // W12^4
        A[2][3] = make_float2(-A[2][3].x, -A[2][3].y);    // W12^6
        float2 Xo[12];
        #pragma unroll
        for (int k1p = 0; k1p < 4; k1p++) {
            float2 b0 = A[0][k1p], b1 = A[1][k1p], b2 = A[2][k1p];
            float2 tt = cadd(b1, b2), dd = csub(b1, b2);
            float2 s  = make_float2(fmaf(-0.5f, tt.x, b0.x),
                                    fmaf(-0.5f, tt.y, b0.y));
            float2 md = mni(dd);
            float2 e  = make_float2(S3 * md.x, S3 * md.y);
            Xo[k1p]     = cadd(b0, tt);
            Xo[k1p + 4] = cadd(s, e);
            Xo[k1p + 8] = csub(s, e);
        }
        // W768^{h0*q} twiddle via recurrence from w1 = W768^{h0}
        sG[(f * 12 + 0) * 65 + h0] = Xo[0];
        float2 w1 = wexp((float)h0 / 384.0f);
        float2 w = w1;
        sG[(f * 12 + 1) * 65 + h0] = cmul(Xo[1], w);
        #pragma unroll
        for (int q = 2; q < 12; q++) {
            w = cmul(w, w1);
            sG[(f * 12 + q) * 65 + h0] = cmul(Xo[q], w);
        }
    }
    __syncthreads();

    // ---- phase 2: 48 independent 64-pt FFTs (radix-8 DIF, 2 stages) ----
    for (int task = t; task < 48 * 8; task += 256) {
        int ff = task % 48, i = task / 48;
        float2* s = &sG[ff * 65];
        float2 v[8];
        #pragma unroll
        for (int j = 0; j < 8; j++) v[j] = s[i + 8 * j];
        dft8(v);
        tw64(v, i);
        #pragma unroll
        for (int j = 0; j < 8; j++) s[i + 8 * j] = v[j];
    }
    __syncthreads();
    for (int task = t; task < 48 * 8; task += 256) {
        int ff = task % 48, blk = task / 48;
        float2* s = &sG[ff * 65 + 8 * blk];
        float2 v[8];
        #pragma unroll
        for (int j = 0; j < 8; j++) v[j] = s[j];
        dft8(v);
        #pragma unroll
        for (int j = 0; j < 8; j++) s[j] = v[j];
    }
    __syncthreads();

    // ---- unpack pairs + write g_Yh[b][s][k] (fp16), slot p = rev(k2)
    for (int k = t; k < KH; k += 256) {
        int k2 = k / 12, k1 = k - k2 * 12;
        int p  = rev8x8(k2);
        int km = (768 - k) % 768;               // conjugate-mirror bin
        int kk2 = km / 12, kk1 = km - kk2 * 12;
        int pk = rev8x8(kk2);
        #pragma unroll
        for (int f = 0; f < 4; f++) {
            float2 Z  = sG[(f * 12 + k1)  * 65 + p];
            float2 Zk = sG[(f * 12 + kk1) * 65 + pk];
            float2 Ya = make_float2(0.5f * (Z.x + Zk.x), 0.5f * (Z.y - Zk.y));
            float2 Yb = make_float2(0.5f * (Z.y + Zk.y), 0.5f * (Zk.x - Z.x));
            g_Yh[((size_t)(b * SEQ) + srow + 2 * f)     * KH + k] = f2h(Ya);
            g_Yh[((size_t)(b * SEQ) + srow + 2 * f + 1) * KH + k] = f2h(Yb);
        }
    }
}

// --------------------------------------- B1: seq FFT step 1 (over s1) + twiddle
// (unchanged from R15 best)
__global__ __launch_bounds__(256) void k_B1() {
    __shared__ float2 tile[64 * KT];   // 16 KB
    int k0 = blockIdx.x * KT;
    int s0 = blockIdx.y;
    int b  = blockIdx.z;
    int t  = threadIdx.x;
    int kk = t & 31, r0 = t >> 5;
    int k  = k0 + kk;
    bool ok = (k < KH);

    float2 v[8];
    #pragma unroll
    for (int j = 0; j < 8; j++)
        v[j] = ok ? h2f(g_Yh[((size_t)(b * SEQ) + s0 + 64 * (r0 + 8 * j)) * KH + k])
                  : make_float2(0.f, 0.f);
    dft8(v);
    tw64(v, r0);                       // W64^{r0*k}
    #pragma unroll
    for (int j = 0; j < 8; j++) tile[(r0 + 8 * j) * KT + kk] = v[j];
    __syncthreads();

    float2 u[8];
    #pragma unroll
    for (int j = 0; j < 8; j++) u[j] = tile[(8 * r0 + j) * KT + kk];
    dft8(u);

    float2 w    = wexp((float)(s0 * r0) / 2048.0f);
    float2 step = wexp((float)(8 * s0) / 2048.0f);
    #pragma unroll
    for (int j = 0; j < 8; j++) {
        int m0 = 8 * j + r0;
        if (ok)
            g_Y2h[(((size_t)b * 64 + m0) * 64 + s0) * KH + k] = f2h(cmul(u[j], w));
        w = cmul(w, step);
    }
}

// --------------------------------------- B2: seq FFT step 2, real part + mirror
// (unchanged from R15 best)
__global__ __launch_bounds__(256) void k_B2(float* __restrict__ out) {
    __shared__ float2 tile[64 * KT];   // 16 KB
    int k0 = blockIdx.x * KT;
    int m0 = blockIdx.y;
    int b  = blockIdx.z;
    int t  = threadIdx.x;
    int kk = t & 31, r0 = t >> 5;
    int k  = k0 + kk;
    bool ok = (k < KH);

    float2 v[8];
    #pragma unroll
    for (int j = 0; j < 8; j++)
        v[j] = ok ? h2f(g_Y2h[(((size_t)b * 64 + m0) * 64 + (r0 + 8 * j)) * KH + k])
                  : make_float2(0.f, 0.f);
    dft8(v);
    tw64(v, r0);
    #pragma unroll
    for (int j = 0; j < 8; j++) tile[(r0 + 8 * j) * KT + kk] = v[j];
    __syncthreads();

    float2 u[8];
    #pragma unroll
    for (int j = 0; j < 8; j++) u[j] = tile[(8 * r0 + j) * KT + kk];
    dft8(u);

    bool domir = (k >= 1 && k <= 383);
    #pragma unroll
    for (int j = 0; j < 8; j++) {
        int m1 = 8 * j + r0;
        float zr = u[j].x;
        int m = m0 + 64 * m1;
        if (ok)
            out[((size_t)b * SEQ + m) * HID + k] = zr;
        if (domir) {
            int mp = (SEQ - m) & 4095;
            out[((size_t)b * SEQ + mp) * HID + (HID - k)] = zr;
        }
    }
}

extern "C" void kernel_launch(void* const* d_in, const int* in_sizes, int n_in,
                              void* d_out, int out_size) {
    (void)in_sizes; (void)n_in; (void)out_size;
    const float* x = (const float*)d_in[0];
    float* out = (float*)d_out;

    k_stageA <<<NB * SEQ / AROWS, 256>>>(x);        // 4096 blocks
    k_B1     <<<dim3(NKT, 64, NB), 256>>>();        // 6656 blocks
    k_B2     <<<dim3(NKT, 64, NB), 256>>>(out);     // 6656 blocks
}